// round 1
// baseline (speedup 1.0000x reference)
#include <cuda_runtime.h>
#include <math.h>

// Problem constants
#define B_   8
#define N_   1024
#define DIM_ 768
#define H_   8
#define HD_  96
// attn element count = B*H*N*N = 67108864

// ---------------- scratch (device globals; no allocation allowed) ----------
__device__ float g_qh[B_*H_*N_*HD_];     // (B,H,N,96)
__device__ float g_kh[B_*H_*N_*HD_];
__device__ float g_vh[B_*H_*N_*HD_];
__device__ float g_attn[67108864];       // (B,H,N,N) 256MB
__device__ float g_ctx[B_*N_*DIM_];      // (B,N,768) pre-projection

// ---------------------------------------------------------------------------
// Kernel 1: 3x3 SAME conv on 16x16x3 token image + head split.
// grid = (B*N, 3) ; block = 256. blockIdx.y selects q/k/v.
// Output layout: (B, H, N, 96).
// ---------------------------------------------------------------------------
__global__ void conv_heads_kernel(const float* __restrict__ q,
                                  const float* __restrict__ k,
                                  const float* __restrict__ v,
                                  const float* __restrict__ w) {
    __shared__ float img[768];
    __shared__ float wt[81];
    int token = blockIdx.x;           // 0..8191
    int which = blockIdx.y;           // 0=q 1=k 2=v
    int tid = threadIdx.x;

    const float* src = (which == 0) ? q : (which == 1) ? k : v;
    float* dst = (which == 0) ? g_qh : (which == 1) ? g_kh : g_vh;

    const float* xp = src + (size_t)token * DIM_;
    for (int i = tid; i < 768; i += 256) img[i] = xp[i];
    if (tid < 81) wt[tid] = w[tid];
    __syncthreads();

    int s = tid >> 4, t = tid & 15;
    float acc0 = 0.f, acc1 = 0.f, acc2 = 0.f;
#pragma unroll
    for (int dy = 0; dy < 3; ++dy) {
        int ys = s + dy - 1;
        bool vy = ((unsigned)ys < 16u);
#pragma unroll
        for (int dx = 0; dx < 3; ++dx) {
            int xs = t + dx - 1;
            if (vy && ((unsigned)xs < 16u)) {
                int base = (ys * 16 + xs) * 3;
                int wb = (dy * 3 + dx) * 9;
#pragma unroll
                for (int ci = 0; ci < 3; ++ci) {
                    float pv = img[base + ci];
                    acc0 += pv * wt[wb + ci * 3 + 0];
                    acc1 += pv * wt[wb + ci * 3 + 1];
                    acc2 += pv * wt[wb + ci * 3 + 2];
                }
            }
        }
    }
    int b = token >> 10, n = token & 1023;
    float accs[3] = {acc0, acc1, acc2};
    int p = tid * 3;
#pragma unroll
    for (int co = 0; co < 3; ++co) {
        int pp = p + co;
        int h = pp / 96;
        int d = pp - h * 96;
        dst[(((size_t)b * H_ + h) * N_ + n) * HD_ + d] = accs[co];
    }
}

// ---------------------------------------------------------------------------
// Kernel 2: QK^T batched SGEMM (NT), C[m][n] = scale * A[m,:].B[n,:], K=96.
// BM=128, BN=64, BK=32, TM=8, TN=4, 256 threads.
// grid = (N/64, N/128, B*H)
// ---------------------------------------------------------------------------
__global__ __launch_bounds__(256)
void qk_gemm_kernel(float scale) {
    __shared__ float As[32][129];
    __shared__ float Bs[32][65];
    int bh = blockIdx.z;
    const float* A = g_qh + (size_t)bh * N_ * HD_;
    const float* Bp = g_kh + (size_t)bh * N_ * HD_;
    float* Cp = g_attn + (size_t)bh * N_ * N_;

    int tid = threadIdx.x;
    int tx = tid & 15, ty = tid >> 4;
    int m0 = blockIdx.y * 128, n0 = blockIdx.x * 64;

    float acc[8][4];
#pragma unroll
    for (int i = 0; i < 8; ++i)
#pragma unroll
        for (int j = 0; j < 4; ++j) acc[i][j] = 0.f;

    for (int k0 = 0; k0 < 96; k0 += 32) {
#pragma unroll
        for (int i = 0; i < 16; ++i) {           // A tile: 128 x 32
            int idx = tid + i * 256;
            int row = idx >> 5, kk = idx & 31;
            As[kk][row] = A[(size_t)(m0 + row) * HD_ + k0 + kk];
        }
#pragma unroll
        for (int i = 0; i < 8; ++i) {            // B tile: 64 x 32
            int idx = tid + i * 256;
            int row = idx >> 5, kk = idx & 31;
            Bs[kk][row] = Bp[(size_t)(n0 + row) * HD_ + k0 + kk];
        }
        __syncthreads();
#pragma unroll
        for (int kk = 0; kk < 32; ++kk) {
            float a[8], bb[4];
#pragma unroll
            for (int i = 0; i < 8; ++i) a[i] = As[kk][ty * 8 + i];
#pragma unroll
            for (int j = 0; j < 4; ++j) bb[j] = Bs[kk][tx * 4 + j];
#pragma unroll
            for (int i = 0; i < 8; ++i)
#pragma unroll
                for (int j = 0; j < 4; ++j) acc[i][j] += a[i] * bb[j];
        }
        __syncthreads();
    }
#pragma unroll
    for (int i = 0; i < 8; ++i) {
        float4 o;
        o.x = acc[i][0] * scale; o.y = acc[i][1] * scale;
        o.z = acc[i][2] * scale; o.w = acc[i][3] * scale;
        *(float4*)&Cp[(size_t)(m0 + ty * 8 + i) * N_ + n0 + tx * 4] = o;
    }
}

// ---------------------------------------------------------------------------
// Kernel 3: fused softmax (per head row) + 8x8 head mix + BatchNorm affine.
// One block per (b, n); all 8 heads' rows (8x1024) in smem. In-place on g_attn.
// grid = B*N, block = 256.
// ---------------------------------------------------------------------------
__global__ __launch_bounds__(256)
void softmax_mix_kernel(const float* __restrict__ rw, const float* __restrict__ rb,
                        const float* __restrict__ gamma, const float* __restrict__ beta,
                        const float* __restrict__ mean, const float* __restrict__ var) {
    __shared__ float buf[8][1024];
    __shared__ float Wm[8][8];
    __shared__ float Cm[8];
    int tid = threadIdx.x;
    int bn = blockIdx.x;
    int b = bn >> 10, n = bn & 1023;

    if (tid < 64) {
        int h = tid >> 3, g = tid & 7;
        float inv = gamma[g] * rsqrtf(var[g] + 1e-3f);
        Wm[h][g] = rw[h * 8 + g] * inv;
        if (h == 0) Cm[g] = (rb[g] - mean[g]) * inv + beta[g];
    }

    size_t base = (size_t)b * 8388608 + (size_t)n * 1024;  // + h*1048576 + m
#pragma unroll 8
    for (int i = 0; i < 32; ++i) {
        int idx = tid + i * 256;
        int h = idx >> 10, m = idx & 1023;
        buf[h][m] = g_attn[base + (size_t)h * 1048576 + m];
    }
    __syncthreads();

    // per-warp softmax: warp w owns head w
    int w = tid >> 5, lane = tid & 31;
    float mx = -1e30f;
    for (int m = lane; m < 1024; m += 32) mx = fmaxf(mx, buf[w][m]);
#pragma unroll
    for (int o = 16; o > 0; o >>= 1) mx = fmaxf(mx, __shfl_xor_sync(0xffffffffu, mx, o));
    float s = 0.f;
    for (int m = lane; m < 1024; m += 32) {
        float e = __expf(buf[w][m] - mx);
        buf[w][m] = e;
        s += e;
    }
#pragma unroll
    for (int o = 16; o > 0; o >>= 1) s += __shfl_xor_sync(0xffffffffu, s, o);
    float invs = 1.0f / s;
    for (int m = lane; m < 1024; m += 32) buf[w][m] *= invs;
    __syncthreads();

    // head mix + BN, write back
    for (int m = tid; m < 1024; m += 256) {
        float p[8];
#pragma unroll
        for (int h = 0; h < 8; ++h) p[h] = buf[h][m];
#pragma unroll
        for (int g = 0; g < 8; ++g) {
            float o = Cm[g];
#pragma unroll
            for (int h = 0; h < 8; ++h) o += p[h] * Wm[h][g];
            g_attn[base + (size_t)g * 1048576 + m] = o;
        }
    }
}

// ---------------------------------------------------------------------------
// Kernel 4: AV batched SGEMM (NN): C[n][d] = sum_m P[n,m] V[m,d], K=1024, Nd=96.
// BM=128, BN=96(full), BK=32, TM=8, TN=6, 256 threads.
// Writes into (B, N, 768) layout for the projection.
// grid = (N/128, B*H)
// ---------------------------------------------------------------------------
__global__ __launch_bounds__(256)
void av_gemm_kernel() {
    __shared__ float As[32][129];
    __shared__ float Bs[32][96];
    int bh = blockIdx.y;
    int b = bh >> 3, h = bh & 7;
    const float* P = g_attn + (size_t)bh * N_ * N_;
    const float* V = g_vh + (size_t)bh * N_ * HD_;

    int tid = threadIdx.x;
    int tx = tid & 15, ty = tid >> 4;
    int n0 = blockIdx.x * 128;

    float acc[8][6];
#pragma unroll
    for (int i = 0; i < 8; ++i)
#pragma unroll
        for (int j = 0; j < 6; ++j) acc[i][j] = 0.f;

    for (int k0 = 0; k0 < N_; k0 += 32) {
#pragma unroll
        for (int i = 0; i < 16; ++i) {           // P tile: 128 x 32
            int idx = tid + i * 256;
            int row = idx >> 5, kk = idx & 31;
            As[kk][row] = P[(size_t)(n0 + row) * N_ + k0 + kk];
        }
#pragma unroll
        for (int i = 0; i < 12; ++i) {           // V tile: 32 x 96
            int idx = tid + i * 256;
            int d = idx % 96, kk = idx / 96;
            Bs[kk][d] = V[(size_t)(k0 + kk) * HD_ + d];
        }
        __syncthreads();
#pragma unroll
        for (int kk = 0; kk < 32; ++kk) {
            float a[8], bb[6];
#pragma unroll
            for (int i = 0; i < 8; ++i) a[i] = As[kk][ty * 8 + i];
#pragma unroll
            for (int j = 0; j < 6; ++j) bb[j] = Bs[kk][tx * 6 + j];
#pragma unroll
            for (int i = 0; i < 8; ++i)
#pragma unroll
                for (int j = 0; j < 6; ++j) acc[i][j] += a[i] * bb[j];
        }
        __syncthreads();
    }
#pragma unroll
    for (int i = 0; i < 8; ++i) {
        size_t row = (size_t)b * N_ + n0 + ty * 8 + i;
#pragma unroll
        for (int j = 0; j < 6; ++j)
            g_ctx[row * DIM_ + h * HD_ + tx * 6 + j] = acc[i][j];
    }
}

// ---------------------------------------------------------------------------
// Kernel 5: projection SGEMM (NN) + bias: out = ctx @ Wp + bp.
// M=8192, N=768, K=768. BM=128, BN=64, BK=32, TM=8, TN=4.
// grid = (768/64, 8192/128)
// ---------------------------------------------------------------------------
__global__ __launch_bounds__(256)
void proj_gemm_kernel(const float* __restrict__ Wp, const float* __restrict__ bp,
                      float* __restrict__ out) {
    __shared__ float As[32][129];
    __shared__ float Bs[32][64];
    int tid = threadIdx.x;
    int tx = tid & 15, ty = tid >> 4;
    int m0 = blockIdx.y * 128, n0 = blockIdx.x * 64;

    float acc[8][4];
#pragma unroll
    for (int i = 0; i < 8; ++i)
#pragma unroll
        for (int j = 0; j < 4; ++j) acc[i][j] = 0.f;

    for (int k0 = 0; k0 < DIM_; k0 += 32) {
#pragma unroll
        for (int i = 0; i < 16; ++i) {           // ctx tile: 128 x 32
            int idx = tid + i * 256;
            int row = idx >> 5, kk = idx & 31;
            As[kk][row] = g_ctx[(size_t)(m0 + row) * DIM_ + k0 + kk];
        }
#pragma unroll
        for (int i = 0; i < 8; ++i) {            // W tile: 32 x 64
            int idx = tid + i * 256;
            int nn = idx & 63, kk = idx >> 6;
            Bs[kk][nn] = Wp[(size_t)(k0 + kk) * DIM_ + n0 + nn];
        }
        __syncthreads();
#pragma unroll
        for (int kk = 0; kk < 32; ++kk) {
            float a[8];
#pragma unroll
            for (int i = 0; i < 8; ++i) a[i] = As[kk][ty * 8 + i];
            float4 b4 = *(const float4*)&Bs[kk][tx * 4];
            float bb[4] = {b4.x, b4.y, b4.z, b4.w};
#pragma unroll
            for (int i = 0; i < 8; ++i)
#pragma unroll
                for (int j = 0; j < 4; ++j) acc[i][j] += a[i] * bb[j];
        }
        __syncthreads();
    }
    float4 bias = *(const float4*)&bp[n0 + tx * 4];
#pragma unroll
    for (int i = 0; i < 8; ++i) {
        float4 o;
        o.x = acc[i][0] + bias.x; o.y = acc[i][1] + bias.y;
        o.z = acc[i][2] + bias.z; o.w = acc[i][3] + bias.w;
        *(float4*)&out[(size_t)(m0 + ty * 8 + i) * DIM_ + n0 + tx * 4] = o;
    }
}

// ---------------------------------------------------------------------------
extern "C" void kernel_launch(void* const* d_in, const int* in_sizes, int n_in,
                              void* d_out, int out_size) {
    const float* q      = (const float*)d_in[0];
    const float* k      = (const float*)d_in[1];
    const float* v      = (const float*)d_in[2];
    const float* conv_w = (const float*)d_in[3];
    const float* rw     = (const float*)d_in[4];
    const float* rb     = (const float*)d_in[5];
    const float* gamma  = (const float*)d_in[6];
    const float* beta   = (const float*)d_in[7];
    const float* mean   = (const float*)d_in[8];
    const float* var    = (const float*)d_in[9];
    const float* pw     = (const float*)d_in[10];
    const float* pb     = (const float*)d_in[11];
    float* out = (float*)d_out;

    float scale = 1.0f / sqrtf((float)HD_);

    conv_heads_kernel<<<dim3(B_ * N_, 3), 256>>>(q, k, v, conv_w);
    qk_gemm_kernel<<<dim3(N_ / 64, N_ / 128, B_ * H_), 256>>>(scale);
    softmax_mix_kernel<<<B_ * N_, 256>>>(rw, rb, gamma, beta, mean, var);
    av_gemm_kernel<<<dim3(N_ / 128, B_ * H_), 256>>>();
    proj_gemm_kernel<<<dim3(DIM_ / 64, (B_ * N_) / 128), 256>>>(pw, pb, out);
}

// round 2
// speedup vs baseline: 2.1037x; 2.1037x over previous
#include <cuda_runtime.h>
#include <math.h>
#include <stdint.h>

// Problem constants
#define B_   8
#define N_   1024
#define DIM_ 768
#define H_   8
#define HD_  96

// ---------------- scratch (device globals; no allocation allowed) ----------
__device__ float g_qh[B_*H_*N_*HD_];     // (B,H,N,96)
__device__ float g_kh[B_*H_*N_*HD_];
__device__ float g_vh[B_*H_*N_*HD_];
__device__ float g_vt[B_*H_*HD_*N_];     // (B,H,96,N)  V transposed
__device__ float g_wt[DIM_*DIM_];        // proj W transposed: [n][k]
__device__ float g_attn[67108864];       // (B,H,N,N) 256MB
__device__ float g_ctx[B_*N_*DIM_];      // (B,N,768) pre-projection

// ---------------------------------------------------------------------------
// helpers: fp32 -> tf32 convert, and m16n8k8 tf32 mma
// ---------------------------------------------------------------------------
__device__ __forceinline__ uint32_t f2tf(float f) {
    uint32_t u;
    asm("cvt.rna.tf32.f32 %0, %1;" : "=r"(u) : "f"(f));
    return u;
}

__device__ __forceinline__ void mma_tf32(float* c, const uint32_t* a, const uint32_t* b) {
    asm volatile(
        "mma.sync.aligned.m16n8k8.row.col.f32.tf32.tf32.f32 "
        "{%0,%1,%2,%3}, {%4,%5,%6,%7}, {%8,%9}, {%0,%1,%2,%3};"
        : "+f"(c[0]), "+f"(c[1]), "+f"(c[2]), "+f"(c[3])
        : "r"(a[0]), "r"(a[1]), "r"(a[2]), "r"(a[3]), "r"(b[0]), "r"(b[1]));
}

// ---------------------------------------------------------------------------
// Kernel 1: 3x3 SAME conv on 16x16x3 token image + head split. (unchanged)
// ---------------------------------------------------------------------------
__global__ void conv_heads_kernel(const float* __restrict__ q,
                                  const float* __restrict__ k,
                                  const float* __restrict__ v,
                                  const float* __restrict__ w) {
    __shared__ float img[768];
    __shared__ float wt[81];
    int token = blockIdx.x;
    int which = blockIdx.y;
    int tid = threadIdx.x;

    const float* src = (which == 0) ? q : (which == 1) ? k : v;
    float* dst = (which == 0) ? g_qh : (which == 1) ? g_kh : g_vh;

    const float* xp = src + (size_t)token * DIM_;
    for (int i = tid; i < 768; i += 256) img[i] = xp[i];
    if (tid < 81) wt[tid] = w[tid];
    __syncthreads();

    int s = tid >> 4, t = tid & 15;
    float acc0 = 0.f, acc1 = 0.f, acc2 = 0.f;
#pragma unroll
    for (int dy = 0; dy < 3; ++dy) {
        int ys = s + dy - 1;
        bool vy = ((unsigned)ys < 16u);
#pragma unroll
        for (int dx = 0; dx < 3; ++dx) {
            int xs = t + dx - 1;
            if (vy && ((unsigned)xs < 16u)) {
                int base = (ys * 16 + xs) * 3;
                int wb = (dy * 3 + dx) * 9;
#pragma unroll
                for (int ci = 0; ci < 3; ++ci) {
                    float pv = img[base + ci];
                    acc0 += pv * wt[wb + ci * 3 + 0];
                    acc1 += pv * wt[wb + ci * 3 + 1];
                    acc2 += pv * wt[wb + ci * 3 + 2];
                }
            }
        }
    }
    int b = token >> 10, n = token & 1023;
    float accs[3] = {acc0, acc1, acc2};
    int p = tid * 3;
#pragma unroll
    for (int co = 0; co < 3; ++co) {
        int pp = p + co;
        int h = pp / 96;
        int d = pp - h * 96;
        dst[(((size_t)b * H_ + h) * N_ + n) * HD_ + d] = accs[co];
    }
}

// ---------------------------------------------------------------------------
// Kernel 2: batched tiled transpose: in (batch, R, C) -> out (batch, C, R)
// grid (C/32, R/32, batch), block (32, 8)
// ---------------------------------------------------------------------------
__global__ void transpose_kernel(const float* __restrict__ in, float* __restrict__ out,
                                 int R, int C) {
    __shared__ float t[32][33];
    int c0 = blockIdx.x * 32, r0 = blockIdx.y * 32;
    const float* ip = in + (size_t)blockIdx.z * R * C;
    float* op = out + (size_t)blockIdx.z * R * C;
    int x = threadIdx.x, y = threadIdx.y;
#pragma unroll
    for (int i = 0; i < 32; i += 8)
        t[y + i][x] = ip[(size_t)(r0 + y + i) * C + c0 + x];
    __syncthreads();
#pragma unroll
    for (int i = 0; i < 32; i += 8)
        op[(size_t)(c0 + y + i) * R + r0 + x] = t[x][y + i];
}

// ---------------------------------------------------------------------------
// Generic TF32 NT GEMM: C[m][n] = scale * sum_k A[m][k]*Bt[n][k]  (+ bias[n])
// BM=128, BK=16, BN template (128 or 96). 256 threads = 8 warps (2 x 4),
// warp tile 64 x WN. Smem stride 20 => conflict-free fragment loads.
// Batched via blockIdx.z: C offset = (z/8)*sCo + (z%8)*sCi.
// ---------------------------------------------------------------------------
template<int BN, int WN>
__global__ __launch_bounds__(256)
void tf32_gemm_nt(const float* __restrict__ A, const float* __restrict__ Bt,
                  float* __restrict__ C,
                  int K, int lda, int ldb, int ldc,
                  long long sA, long long sB, long long sCo, long long sCi,
                  float scale, const float* __restrict__ bias) {
    constexpr int NF = WN / 8;              // n-frags per warp (4 or 3)
    constexpr int AB_WORDS = 128 * 20 + BN * 20;
    constexpr int CS_WORDS = 128 * (WN + 4);
    constexpr int SM_WORDS = AB_WORDS > CS_WORDS ? AB_WORDS : CS_WORDS;
    __shared__ __align__(16) uint32_t smraw[SM_WORDS];
    uint32_t* As = smraw;
    uint32_t* Bs = smraw + 128 * 20;
    float* Cs = (float*)smraw;

    int z = blockIdx.z;
    A += (size_t)z * sA;
    Bt += (size_t)z * sB;
    C += (size_t)(z >> 3) * sCo + (size_t)(z & 7) * sCi;

    int tid = threadIdx.x;
    int lane = tid & 31, w = tid >> 5;
    int wm = w >> 2, wn = w & 3;
    int gid = lane >> 2, tig = lane & 3;
    int m0 = blockIdx.y * 128, n0 = blockIdx.x * BN;

    float acc[4][NF][4];
#pragma unroll
    for (int i = 0; i < 4; ++i)
#pragma unroll
        for (int j = 0; j < NF; ++j)
#pragma unroll
            for (int r = 0; r < 4; ++r) acc[i][j][r] = 0.f;

    for (int k0 = 0; k0 < K; k0 += 16) {
        // load A tile: 128 x 16 (512 float4 over 256 threads)
#pragma unroll
        for (int it = 0; it < 2; ++it) {
            int idx = tid + it * 256;
            int row = idx >> 2, c4 = (idx & 3) * 4;
            float4 f = *(const float4*)&A[(size_t)(m0 + row) * lda + k0 + c4];
            uint4 u = make_uint4(f2tf(f.x), f2tf(f.y), f2tf(f.z), f2tf(f.w));
            *(uint4*)&As[row * 20 + c4] = u;
        }
        // load B tile: BN x 16
#pragma unroll
        for (int it = 0; it < (BN * 4 + 255) / 256; ++it) {
            int idx = tid + it * 256;
            if (idx < BN * 4) {
                int row = idx >> 2, c4 = (idx & 3) * 4;
                float4 f = *(const float4*)&Bt[(size_t)(n0 + row) * ldb + k0 + c4];
                uint4 u = make_uint4(f2tf(f.x), f2tf(f.y), f2tf(f.z), f2tf(f.w));
                *(uint4*)&Bs[row * 20 + c4] = u;
            }
        }
        __syncthreads();
#pragma unroll
        for (int kk = 0; kk < 16; kk += 8) {
            uint32_t a[4][4];
#pragma unroll
            for (int i = 0; i < 4; ++i) {
                int arow = wm * 64 + i * 16 + gid;
                a[i][0] = As[arow * 20 + kk + tig];
                a[i][1] = As[(arow + 8) * 20 + kk + tig];
                a[i][2] = As[arow * 20 + kk + tig + 4];
                a[i][3] = As[(arow + 8) * 20 + kk + tig + 4];
            }
            uint32_t b[NF][2];
#pragma unroll
            for (int j = 0; j < NF; ++j) {
                int brow = wn * WN + j * 8 + gid;
                b[j][0] = Bs[brow * 20 + kk + tig];
                b[j][1] = Bs[brow * 20 + kk + tig + 4];
            }
#pragma unroll
            for (int i = 0; i < 4; ++i)
#pragma unroll
                for (int j = 0; j < NF; ++j)
                    mma_tf32(acc[i][j], a[i], b[j]);
        }
        __syncthreads();
    }

    // epilogue: 4 chunks of WN cols, staged through smem for coalesced stores
    constexpr int W4 = WN / 4;
#pragma unroll 1
    for (int c = 0; c < 4; ++c) {
        __syncthreads();
        if (wn == c) {
#pragma unroll
            for (int i = 0; i < 4; ++i)
#pragma unroll
                for (int j = 0; j < NF; ++j) {
                    int r = wm * 64 + i * 16 + gid;
                    int cc = j * 8 + tig * 2;
                    Cs[r * (WN + 4) + cc]       = acc[i][j][0];
                    Cs[r * (WN + 4) + cc + 1]   = acc[i][j][1];
                    Cs[(r + 8) * (WN + 4) + cc]     = acc[i][j][2];
                    Cs[(r + 8) * (WN + 4) + cc + 1] = acc[i][j][3];
                }
        }
        __syncthreads();
        int ngl0 = n0 + c * WN;
        for (int idx = tid; idx < 128 * W4; idx += 256) {
            int row = idx / W4, c4 = (idx % W4) * 4;
            float4 v = *(float4*)&Cs[row * (WN + 4) + c4];
            v.x *= scale; v.y *= scale; v.z *= scale; v.w *= scale;
            if (bias) {
                v.x += bias[ngl0 + c4];
                v.y += bias[ngl0 + c4 + 1];
                v.z += bias[ngl0 + c4 + 2];
                v.w += bias[ngl0 + c4 + 3];
            }
            *(float4*)&C[(size_t)(m0 + row) * ldc + ngl0 + c4] = v;
        }
    }
}

// ---------------------------------------------------------------------------
// Kernel: fused softmax (per head row) + 8x8 head mix + BatchNorm. (unchanged)
// ---------------------------------------------------------------------------
__global__ __launch_bounds__(256)
void softmax_mix_kernel(const float* __restrict__ rw, const float* __restrict__ rb,
                        const float* __restrict__ gamma, const float* __restrict__ beta,
                        const float* __restrict__ mean, const float* __restrict__ var) {
    __shared__ float buf[8][1024];
    __shared__ float Wm[8][8];
    __shared__ float Cm[8];
    int tid = threadIdx.x;
    int bn = blockIdx.x;
    int b = bn >> 10, n = bn & 1023;

    if (tid < 64) {
        int h = tid >> 3, g = tid & 7;
        float inv = gamma[g] * rsqrtf(var[g] + 1e-3f);
        Wm[h][g] = rw[h * 8 + g] * inv;
        if (h == 0) Cm[g] = (rb[g] - mean[g]) * inv + beta[g];
    }

    size_t base = (size_t)b * 8388608 + (size_t)n * 1024;
#pragma unroll 8
    for (int i = 0; i < 32; ++i) {
        int idx = tid + i * 256;
        int h = idx >> 10, m = idx & 1023;
        buf[h][m] = g_attn[base + (size_t)h * 1048576 + m];
    }
    __syncthreads();

    int w = tid >> 5, lane = tid & 31;
    float mx = -1e30f;
    for (int m = lane; m < 1024; m += 32) mx = fmaxf(mx, buf[w][m]);
#pragma unroll
    for (int o = 16; o > 0; o >>= 1) mx = fmaxf(mx, __shfl_xor_sync(0xffffffffu, mx, o));
    float s = 0.f;
    for (int m = lane; m < 1024; m += 32) {
        float e = __expf(buf[w][m] - mx);
        buf[w][m] = e;
        s += e;
    }
#pragma unroll
    for (int o = 16; o > 0; o >>= 1) s += __shfl_xor_sync(0xffffffffu, s, o);
    float invs = 1.0f / s;
    for (int m = lane; m < 1024; m += 32) buf[w][m] *= invs;
    __syncthreads();

    for (int m = tid; m < 1024; m += 256) {
        float p[8];
#pragma unroll
        for (int h = 0; h < 8; ++h) p[h] = buf[h][m];
#pragma unroll
        for (int g = 0; g < 8; ++g) {
            float o = Cm[g];
#pragma unroll
            for (int h = 0; h < 8; ++h) o += p[h] * Wm[h][g];
            g_attn[base + (size_t)g * 1048576 + m] = o;
        }
    }
}

// ---------------------------------------------------------------------------
extern "C" void kernel_launch(void* const* d_in, const int* in_sizes, int n_in,
                              void* d_out, int out_size) {
    const float* q      = (const float*)d_in[0];
    const float* k      = (const float*)d_in[1];
    const float* v      = (const float*)d_in[2];
    const float* conv_w = (const float*)d_in[3];
    const float* rw     = (const float*)d_in[4];
    const float* rb     = (const float*)d_in[5];
    const float* gamma  = (const float*)d_in[6];
    const float* beta   = (const float*)d_in[7];
    const float* mean   = (const float*)d_in[8];
    const float* var    = (const float*)d_in[9];
    const float* pw     = (const float*)d_in[10];
    const float* pb     = (const float*)d_in[11];
    float* out = (float*)d_out;

    float scale = 1.0f / sqrtf((float)HD_);

    float *qh, *kh, *vh, *vt, *wt, *attn, *ctx;
    cudaGetSymbolAddress((void**)&qh, g_qh);
    cudaGetSymbolAddress((void**)&kh, g_kh);
    cudaGetSymbolAddress((void**)&vh, g_vh);
    cudaGetSymbolAddress((void**)&vt, g_vt);
    cudaGetSymbolAddress((void**)&wt, g_wt);
    cudaGetSymbolAddress((void**)&attn, g_attn);
    cudaGetSymbolAddress((void**)&ctx, g_ctx);

    // 1. conv + head split
    conv_heads_kernel<<<dim3(B_ * N_, 3), 256>>>(q, k, v, conv_w);

    // 2. transposes: V -> (B,H,96,N), W -> [n][k]
    transpose_kernel<<<dim3(HD_ / 32, N_ / 32, B_ * H_), dim3(32, 8)>>>(vh, vt, N_, HD_);
    transpose_kernel<<<dim3(DIM_ / 32, DIM_ / 32, 1), dim3(32, 8)>>>(pw, wt, DIM_, DIM_);

    // 3. QK^T (scaled): A=Q (N x 96), B=K (N x 96), C=attn (N x N) per (b,h)
    tf32_gemm_nt<128, 32><<<dim3(N_ / 128, N_ / 128, B_ * H_), 256>>>(
        qh, kh, attn, HD_, HD_, HD_, N_,
        (long long)N_ * HD_, (long long)N_ * HD_,
        (long long)H_ * N_ * N_, (long long)N_ * N_,
        scale, nullptr);

    // 4. softmax + head mix + BN (in place on attn)
    softmax_mix_kernel<<<B_ * N_, 256>>>(rw, rb, gamma, beta, mean, var);

    // 5. AV: A=attn (N x N), B=Vt (96 x N), C -> ctx (B,N,768) col block h*96
    tf32_gemm_nt<96, 24><<<dim3(1, N_ / 128, B_ * H_), 256>>>(
        attn, vt, ctx, N_, N_, N_, DIM_,
        (long long)N_ * N_, (long long)HD_ * N_,
        (long long)N_ * DIM_, (long long)HD_,
        1.0f, nullptr);

    // 6. projection + bias: A=ctx (8192 x 768), B=Wt (768 x 768), C=out
    tf32_gemm_nt<128, 32><<<dim3(DIM_ / 128, (B_ * N_) / 128, 1), 256>>>(
        ctx, wt, out, DIM_, DIM_, DIM_, DIM_,
        0LL, 0LL, 0LL, 0LL,
        1.0f, pb);
}

// round 3
// speedup vs baseline: 2.9102x; 1.3834x over previous
#include <cuda_runtime.h>
#include <math.h>
#include <stdint.h>

// Problem constants
#define B_   8
#define N_   1024
#define DIM_ 768
#define H_   8
#define HD_  96

// ---------------- scratch (device globals; no allocation allowed) ----------
__device__ float g_qh[B_*H_*N_*HD_];     // (B,H,N,96)   tf32-rounded
__device__ float g_kh[B_*H_*N_*HD_];
__device__ float g_vh[B_*H_*N_*HD_];
__device__ float g_vt[B_*H_*HD_*N_];     // (B,H,96,N)   tf32-rounded
__device__ float g_wt[DIM_*DIM_];        // proj W transposed [n][k], tf32-rounded
__device__ float g_attn[67108864];       // (B,H,N,N) 256MB
__device__ float g_ctx[B_*N_*DIM_];      // (B,N,768)    tf32-rounded

// ---------------------------------------------------------------------------
__device__ __forceinline__ uint32_t f2tf(float f) {
    uint32_t u;
    asm("cvt.rna.tf32.f32 %0, %1;" : "=r"(u) : "f"(f));
    return u;
}
__device__ __forceinline__ float f2tff(float f) { return __uint_as_float(f2tf(f)); }

__device__ __forceinline__ void mma_tf32(float* c, const uint32_t* a, const uint32_t* b) {
    asm volatile(
        "mma.sync.aligned.m16n8k8.row.col.f32.tf32.tf32.f32 "
        "{%0,%1,%2,%3}, {%4,%5,%6,%7}, {%8,%9}, {%0,%1,%2,%3};"
        : "+f"(c[0]), "+f"(c[1]), "+f"(c[2]), "+f"(c[3])
        : "r"(a[0]), "r"(a[1]), "r"(a[2]), "r"(a[3]), "r"(b[0]), "r"(b[1]));
}

__device__ __forceinline__ void cp_async16(void* smem, const void* gmem) {
    uint32_t s = (uint32_t)__cvta_generic_to_shared(smem);
    asm volatile("cp.async.cg.shared.global [%0], [%1], 16;" :: "r"(s), "l"(gmem));
}
#define CP_COMMIT asm volatile("cp.async.commit_group;")
#define CP_WAIT1  asm volatile("cp.async.wait_group 1;")
#define CP_WAIT0  asm volatile("cp.async.wait_group 0;")

// ---------------------------------------------------------------------------
// Kernel 1: 3x3 SAME conv on 16x16x3 token image + head split (tf32-rounded out)
// ---------------------------------------------------------------------------
__global__ void conv_heads_kernel(const float* __restrict__ q,
                                  const float* __restrict__ k,
                                  const float* __restrict__ v,
                                  const float* __restrict__ w) {
    __shared__ float img[768];
    __shared__ float wt[81];
    int token = blockIdx.x;
    int which = blockIdx.y;
    int tid = threadIdx.x;

    const float* src = (which == 0) ? q : (which == 1) ? k : v;
    float* dst = (which == 0) ? g_qh : (which == 1) ? g_kh : g_vh;

    const float* xp = src + (size_t)token * DIM_;
    for (int i = tid; i < 768; i += 256) img[i] = xp[i];
    if (tid < 81) wt[tid] = w[tid];
    __syncthreads();

    int s = tid >> 4, t = tid & 15;
    float acc0 = 0.f, acc1 = 0.f, acc2 = 0.f;
#pragma unroll
    for (int dy = 0; dy < 3; ++dy) {
        int ys = s + dy - 1;
        bool vy = ((unsigned)ys < 16u);
#pragma unroll
        for (int dx = 0; dx < 3; ++dx) {
            int xs = t + dx - 1;
            if (vy && ((unsigned)xs < 16u)) {
                int base = (ys * 16 + xs) * 3;
                int wb = (dy * 3 + dx) * 9;
#pragma unroll
                for (int ci = 0; ci < 3; ++ci) {
                    float pv = img[base + ci];
                    acc0 += pv * wt[wb + ci * 3 + 0];
                    acc1 += pv * wt[wb + ci * 3 + 1];
                    acc2 += pv * wt[wb + ci * 3 + 2];
                }
            }
        }
    }
    int b = token >> 10, n = token & 1023;
    float accs[3] = {acc0, acc1, acc2};
    int p = tid * 3;
#pragma unroll
    for (int co = 0; co < 3; ++co) {
        int pp = p + co;
        int h = pp / 96;
        int d = pp - h * 96;
        dst[(((size_t)b * H_ + h) * N_ + n) * HD_ + d] = f2tff(accs[co]);
    }
}

// ---------------------------------------------------------------------------
// Kernel 2: batched tiled transpose + tf32 round: (batch,R,C) -> (batch,C,R)
// ---------------------------------------------------------------------------
__global__ void transpose_kernel(const float* __restrict__ in, float* __restrict__ out,
                                 int R, int C) {
    __shared__ float t[32][33];
    int c0 = blockIdx.x * 32, r0 = blockIdx.y * 32;
    const float* ip = in + (size_t)blockIdx.z * R * C;
    float* op = out + (size_t)blockIdx.z * R * C;
    int x = threadIdx.x, y = threadIdx.y;
#pragma unroll
    for (int i = 0; i < 32; i += 8)
        t[y + i][x] = ip[(size_t)(r0 + y + i) * C + c0 + x];
    __syncthreads();
#pragma unroll
    for (int i = 0; i < 32; i += 8)
        op[(size_t)(c0 + y + i) * R + r0 + x] = f2tff(t[x][y + i]);
}

// ---------------------------------------------------------------------------
// TF32 NT GEMM, cp.async double-buffered.
// C[m][n] = scale * sum_k A[m][k]*Bt[n][k] (+ bias[n]) [optional tf32 round]
// BM=128, BK=16, BN in {128,96}. 256 threads = 8 warps (2x4), warp tile 64xWN.
// Inputs must be pre-rounded to tf32. Batched via blockIdx.z.
// ---------------------------------------------------------------------------
template<int BN, int WN>
__global__ __launch_bounds__(256)
void tf32_gemm_nt(const float* __restrict__ A, const float* __restrict__ Bt,
                  float* __restrict__ C,
                  int K, int lda, int ldb, int ldc,
                  long long sA, long long sB, long long sCo, long long sCi,
                  float scale, const float* __restrict__ bias, int round_out) {
    constexpr int NF = WN / 8;
    __shared__ __align__(16) uint32_t As[2][128 * 20];
    __shared__ __align__(16) uint32_t Bs[2][BN * 20];

    int z = blockIdx.z;
    A += (size_t)z * sA;
    Bt += (size_t)z * sB;
    C += (size_t)(z >> 3) * sCo + (size_t)(z & 7) * sCi;

    int tid = threadIdx.x;
    int lane = tid & 31, w = tid >> 5;
    int wm = w >> 2, wn = w & 3;
    int gid = lane >> 2, tig = lane & 3;
    int m0 = blockIdx.y * 128, n0 = blockIdx.x * BN;

    float acc[4][NF][4];
#pragma unroll
    for (int i = 0; i < 4; ++i)
#pragma unroll
        for (int j = 0; j < NF; ++j)
#pragma unroll
            for (int r = 0; r < 4; ++r) acc[i][j][r] = 0.f;

    int T = K >> 4;

    auto load_tile = [&](int t, int stg) {
        int k0 = t * 16;
#pragma unroll
        for (int it = 0; it < 2; ++it) {
            int idx = tid + it * 256;
            int row = idx >> 2, c4 = (idx & 3) * 4;
            cp_async16(&As[stg][row * 20 + c4], &A[(size_t)(m0 + row) * lda + k0 + c4]);
        }
#pragma unroll
        for (int it = 0; it < (BN * 4 + 255) / 256; ++it) {
            int idx = tid + it * 256;
            if (BN == 128 || idx < BN * 4) {
                int row = idx >> 2, c4 = (idx & 3) * 4;
                cp_async16(&Bs[stg][row * 20 + c4], &Bt[(size_t)(n0 + row) * ldb + k0 + c4]);
            }
        }
    };

    load_tile(0, 0); CP_COMMIT;
    for (int t = 0; t < T; ++t) {
        int cur = t & 1;
        if (t + 1 < T) { load_tile(t + 1, cur ^ 1); CP_COMMIT; CP_WAIT1; }
        else          { CP_WAIT0; }
        __syncthreads();
#pragma unroll
        for (int kk = 0; kk < 16; kk += 8) {
            uint32_t a[4][4];
#pragma unroll
            for (int i = 0; i < 4; ++i) {
                int arow = wm * 64 + i * 16 + gid;
                a[i][0] = As[cur][arow * 20 + kk + tig];
                a[i][1] = As[cur][(arow + 8) * 20 + kk + tig];
                a[i][2] = As[cur][arow * 20 + kk + tig + 4];
                a[i][3] = As[cur][(arow + 8) * 20 + kk + tig + 4];
            }
            uint32_t b[NF][2];
#pragma unroll
            for (int j = 0; j < NF; ++j) {
                int brow = wn * WN + j * 8 + gid;
                b[j][0] = Bs[cur][brow * 20 + kk + tig];
                b[j][1] = Bs[cur][brow * 20 + kk + tig + 4];
            }
#pragma unroll
            for (int i = 0; i < 4; ++i)
#pragma unroll
                for (int j = 0; j < NF; ++j)
                    mma_tf32(acc[i][j], a[i], b[j]);
        }
        __syncthreads();
    }

    // direct float2 epilogue
#pragma unroll
    for (int i = 0; i < 4; ++i) {
        int r = m0 + wm * 64 + i * 16 + gid;
#pragma unroll
        for (int j = 0; j < NF; ++j) {
            int cgl = n0 + wn * WN + j * 8 + tig * 2;
            float2 v0, v1;
            v0.x = acc[i][j][0] * scale; v0.y = acc[i][j][1] * scale;
            v1.x = acc[i][j][2] * scale; v1.y = acc[i][j][3] * scale;
            if (bias) {
                float bx = bias[cgl], by = bias[cgl + 1];
                v0.x += bx; v0.y += by; v1.x += bx; v1.y += by;
            }
            if (round_out) {
                v0.x = f2tff(v0.x); v0.y = f2tff(v0.y);
                v1.x = f2tff(v1.x); v1.y = f2tff(v1.y);
            }
            *(float2*)&C[(size_t)r * ldc + cgl] = v0;
            *(float2*)&C[(size_t)(r + 8) * ldc + cgl] = v1;
        }
    }
}

// ---------------------------------------------------------------------------
// Fused softmax + 8x8 head mix + BN, vectorized float4, in-place on g_attn.
// One block per (b,n). Normalization folded into the mix. Output tf32-rounded.
// ---------------------------------------------------------------------------
__global__ __launch_bounds__(256)
void softmax_mix_kernel(const float* __restrict__ rw, const float* __restrict__ rb,
                        const float* __restrict__ gamma, const float* __restrict__ beta,
                        const float* __restrict__ mean, const float* __restrict__ var) {
    __shared__ float buf[8][1024];
    __shared__ float Wm[8][8];
    __shared__ float Cm[8];
    __shared__ float invsS[8];
    int tid = threadIdx.x;
    int bn = blockIdx.x;
    int b = bn >> 10, n = bn & 1023;

    if (tid < 64) {
        int h = tid >> 3, g = tid & 7;
        float inv = gamma[g] * rsqrtf(var[g] + 1e-3f);
        Wm[h][g] = rw[h * 8 + g] * inv;
        if (h == 0) Cm[g] = (rb[g] - mean[g]) * inv + beta[g];
    }

    size_t base = (size_t)b * 8388608 + (size_t)n * 1024;
    const float4* gin = (const float4*)(g_attn + base);
    float4* bf4 = (float4*)&buf[0][0];
#pragma unroll
    for (int i = 0; i < 8; ++i) {
        int idx = tid + i * 256;                 // 0..2047 float4s
        int h = idx >> 8, m4 = idx & 255;
        bf4[idx] = gin[(size_t)h * 262144 + m4];
    }
    __syncthreads();

    // per-warp softmax stats on head w (unnormalized exp kept in buf)
    int w = tid >> 5, lane = tid & 31;
    float4* bw = (float4*)buf[w];
    float mx = -1e30f;
#pragma unroll
    for (int ii = 0; ii < 8; ++ii) {
        float4 p = bw[lane + ii * 32];
        mx = fmaxf(mx, fmaxf(fmaxf(p.x, p.y), fmaxf(p.z, p.w)));
    }
#pragma unroll
    for (int o = 16; o > 0; o >>= 1) mx = fmaxf(mx, __shfl_xor_sync(0xffffffffu, mx, o));
    float s = 0.f;
#pragma unroll
    for (int ii = 0; ii < 8; ++ii) {
        float4 p = bw[lane + ii * 32];
        p.x = __expf(p.x - mx); p.y = __expf(p.y - mx);
        p.z = __expf(p.z - mx); p.w = __expf(p.w - mx);
        bw[lane + ii * 32] = p;
        s += p.x + p.y + p.z + p.w;
    }
#pragma unroll
    for (int o = 16; o > 0; o >>= 1) s += __shfl_xor_sync(0xffffffffu, s, o);
    if (lane == 0) invsS[w] = 1.0f / s;
    __syncthreads();

    // mix heads (normalization folded), one float4 per thread per head
    float4 p[8];
#pragma unroll
    for (int h = 0; h < 8; ++h) {
        float inv = invsS[h];
        float4 t = ((float4*)buf[h])[tid];
        p[h].x = t.x * inv; p[h].y = t.y * inv; p[h].z = t.z * inv; p[h].w = t.w * inv;
    }
    float4* gout = (float4*)(g_attn + base);
#pragma unroll
    for (int g = 0; g < 8; ++g) {
        float4 o;
        float c = Cm[g];
        o.x = c; o.y = c; o.z = c; o.w = c;
#pragma unroll
        for (int h = 0; h < 8; ++h) {
            float wv = Wm[h][g];
            o.x += p[h].x * wv; o.y += p[h].y * wv;
            o.z += p[h].z * wv; o.w += p[h].w * wv;
        }
        o.x = f2tff(o.x); o.y = f2tff(o.y); o.z = f2tff(o.z); o.w = f2tff(o.w);
        gout[(size_t)g * 262144 + tid] = o;
    }
}

// ---------------------------------------------------------------------------
extern "C" void kernel_launch(void* const* d_in, const int* in_sizes, int n_in,
                              void* d_out, int out_size) {
    const float* q      = (const float*)d_in[0];
    const float* k      = (const float*)d_in[1];
    const float* v      = (const float*)d_in[2];
    const float* conv_w = (const float*)d_in[3];
    const float* rw     = (const float*)d_in[4];
    const float* rb     = (const float*)d_in[5];
    const float* gamma  = (const float*)d_in[6];
    const float* beta   = (const float*)d_in[7];
    const float* mean   = (const float*)d_in[8];
    const float* var    = (const float*)d_in[9];
    const float* pw     = (const float*)d_in[10];
    const float* pb     = (const float*)d_in[11];
    float* out = (float*)d_out;

    float scale = 1.0f / sqrtf((float)HD_);

    float *qh, *kh, *vh, *vt, *wt, *attn, *ctx;
    cudaGetSymbolAddress((void**)&qh, g_qh);
    cudaGetSymbolAddress((void**)&kh, g_kh);
    cudaGetSymbolAddress((void**)&vh, g_vh);
    cudaGetSymbolAddress((void**)&vt, g_vt);
    cudaGetSymbolAddress((void**)&wt, g_wt);
    cudaGetSymbolAddress((void**)&attn, g_attn);
    cudaGetSymbolAddress((void**)&ctx, g_ctx);

    // 1. conv + head split (tf32-rounded outputs)
    conv_heads_kernel<<<dim3(B_ * N_, 3), 256>>>(q, k, v, conv_w);

    // 2. transposes (tf32-rounded): V -> (B,H,96,N), W -> [n][k]
    transpose_kernel<<<dim3(HD_ / 32, N_ / 32, B_ * H_), dim3(32, 8)>>>(vh, vt, N_, HD_);
    transpose_kernel<<<dim3(DIM_ / 32, DIM_ / 32, 1), dim3(32, 8)>>>(pw, wt, DIM_, DIM_);

    // 3. QK^T (scaled)
    tf32_gemm_nt<128, 32><<<dim3(N_ / 128, N_ / 128, B_ * H_), 256>>>(
        qh, kh, attn, HD_, HD_, HD_, N_,
        (long long)N_ * HD_, (long long)N_ * HD_,
        (long long)H_ * N_ * N_, (long long)N_ * N_,
        scale, nullptr, 0);

    // 4. softmax + head mix + BN (in place, tf32-rounded)
    softmax_mix_kernel<<<B_ * N_, 256>>>(rw, rb, gamma, beta, mean, var);

    // 5. AV -> ctx (B,N,768), tf32-rounded for projection
    tf32_gemm_nt<96, 24><<<dim3(1, N_ / 128, B_ * H_), 256>>>(
        attn, vt, ctx, N_, N_, N_, DIM_,
        (long long)N_ * N_, (long long)HD_ * N_,
        (long long)N_ * DIM_, (long long)HD_,
        1.0f, nullptr, 1);

    // 6. projection + bias -> out
    tf32_gemm_nt<128, 32><<<dim3(DIM_ / 128, (B_ * N_) / 128, 1), 256>>>(
        ctx, wt, out, DIM_, DIM_, DIM_, DIM_,
        0LL, 0LL, 0LL, 0LL,
        1.0f, pb, 0);
}

// round 4
// speedup vs baseline: 4.0359x; 1.3868x over previous
#include <cuda_runtime.h>
#include <cuda_fp16.h>
#include <math.h>
#include <stdint.h>

// Problem constants
#define B_   8
#define N_   1024
#define DIM_ 768
#define H_   8
#define HD_  96

// ---------------- scratch (device globals; no allocation allowed) ----------
__device__ __align__(256) __half g_qh[B_*H_*N_*HD_];   // (B,H,N,96) fp16
__device__ __align__(256) __half g_kh[B_*H_*N_*HD_];
__device__ __align__(256) __half g_vh[B_*H_*N_*HD_];
__device__ __align__(256) __half g_vt[B_*H_*HD_*N_];   // (B,H,96,N) fp16
__device__ __align__(256) __half g_wt[DIM_*DIM_];      // proj W^T [n][k] fp16
__device__ __align__(256) float  g_attn[67108864];     // S logits (B,H,N,N) fp32
__device__ __align__(256) __half g_p[67108864];        // P (post softmax+mix) fp16
__device__ __align__(256) __half g_ctx[B_*N_*DIM_];    // (B,N,768) fp16

// ---------------------------------------------------------------------------
__device__ __forceinline__ void mma_f16(float* c, const uint32_t* a, const uint32_t* b) {
    asm volatile(
        "mma.sync.aligned.m16n8k16.row.col.f32.f16.f16.f32 "
        "{%0,%1,%2,%3}, {%4,%5,%6,%7}, {%8,%9}, {%0,%1,%2,%3};"
        : "+f"(c[0]), "+f"(c[1]), "+f"(c[2]), "+f"(c[3])
        : "r"(a[0]), "r"(a[1]), "r"(a[2]), "r"(a[3]), "r"(b[0]), "r"(b[1]));
}

__device__ __forceinline__ void cp_async16(void* smem, const void* gmem) {
    uint32_t s = (uint32_t)__cvta_generic_to_shared(smem);
    asm volatile("cp.async.cg.shared.global [%0], [%1], 16;" :: "r"(s), "l"(gmem));
}
#define CP_COMMIT asm volatile("cp.async.commit_group;")
#define CP_WAIT1  asm volatile("cp.async.wait_group 1;")
#define CP_WAIT0  asm volatile("cp.async.wait_group 0;")

// ---------------------------------------------------------------------------
// Kernel 1: 3x3 SAME conv on 16x16x3 token image + head split -> fp16
// ---------------------------------------------------------------------------
__global__ void conv_heads_kernel(const float* __restrict__ q,
                                  const float* __restrict__ k,
                                  const float* __restrict__ v,
                                  const float* __restrict__ w) {
    __shared__ float img[768];
    __shared__ float wt[81];
    int token = blockIdx.x;
    int which = blockIdx.y;
    int tid = threadIdx.x;

    const float* src = (which == 0) ? q : (which == 1) ? k : v;
    __half* dst = (which == 0) ? g_qh : (which == 1) ? g_kh : g_vh;

    const float* xp = src + (size_t)token * DIM_;
    for (int i = tid; i < 768; i += 256) img[i] = xp[i];
    if (tid < 81) wt[tid] = w[tid];
    __syncthreads();

    int s = tid >> 4, t = tid & 15;
    float acc0 = 0.f, acc1 = 0.f, acc2 = 0.f;
#pragma unroll
    for (int dy = 0; dy < 3; ++dy) {
        int ys = s + dy - 1;
        bool vy = ((unsigned)ys < 16u);
#pragma unroll
        for (int dx = 0; dx < 3; ++dx) {
            int xs = t + dx - 1;
            if (vy && ((unsigned)xs < 16u)) {
                int base = (ys * 16 + xs) * 3;
                int wb = (dy * 3 + dx) * 9;
#pragma unroll
                for (int ci = 0; ci < 3; ++ci) {
                    float pv = img[base + ci];
                    acc0 += pv * wt[wb + ci * 3 + 0];
                    acc1 += pv * wt[wb + ci * 3 + 1];
                    acc2 += pv * wt[wb + ci * 3 + 2];
                }
            }
        }
    }
    int b = token >> 10, n = token & 1023;
    float accs[3] = {acc0, acc1, acc2};
    int p = tid * 3;
#pragma unroll
    for (int co = 0; co < 3; ++co) {
        int pp = p + co;
        int h = pp / 96;
        int d = pp - h * 96;
        dst[(((size_t)b * H_ + h) * N_ + n) * HD_ + d] = __float2half_rn(accs[co]);
    }
}

// ---------------------------------------------------------------------------
// Kernel 2: batched tiled transpose: (batch,R,C) -> (batch,C,R), TI -> half
// ---------------------------------------------------------------------------
template<typename TI>
__global__ void transpose_kernel(const TI* __restrict__ in, __half* __restrict__ out,
                                 int R, int C) {
    __shared__ float t[32][33];
    int c0 = blockIdx.x * 32, r0 = blockIdx.y * 32;
    const TI* ip = in + (size_t)blockIdx.z * R * C;
    __half* op = out + (size_t)blockIdx.z * R * C;
    int x = threadIdx.x, y = threadIdx.y;
#pragma unroll
    for (int i = 0; i < 32; i += 8)
        t[y + i][x] = (float)ip[(size_t)(r0 + y + i) * C + c0 + x];
    __syncthreads();
#pragma unroll
    for (int i = 0; i < 32; i += 8)
        op[(size_t)(c0 + y + i) * R + r0 + x] = __float2half_rn(t[x][y + i]);
}

// ---------------------------------------------------------------------------
// FP16 NT GEMM (fp32 accum), cp.async double-buffered.
// C[m][n] = scale * sum_k A[m][k]*Bt[n][k] (+ bias[n]).
// BM=128, BK=32 halves, BN in {128,96}. 256 thr = 8 warps (2x4), warp 64xWN.
// Smem: packed half2 in uint32, row stride 20 uints -> conflict-free.
// HALF_OUT: write __half C, else float C. Batched via blockIdx.z.
// ---------------------------------------------------------------------------
template<int BN, int WN, bool HALF_OUT>
__global__ __launch_bounds__(256)
void f16_gemm_nt(const __half* __restrict__ A, const __half* __restrict__ Bt,
                 void* __restrict__ Cv,
                 int K, int lda, int ldb, int ldc,
                 long long sA, long long sB, long long sCo, long long sCi,
                 float scale, const float* __restrict__ bias) {
    constexpr int NF = WN / 8;
    __shared__ __align__(16) uint32_t As[2][128 * 20];
    __shared__ __align__(16) uint32_t Bs[2][BN * 20];

    int z = blockIdx.z;
    A += (size_t)z * sA;
    Bt += (size_t)z * sB;
    size_t coff = (size_t)(z >> 3) * sCo + (size_t)(z & 7) * sCi;

    int tid = threadIdx.x;
    int lane = tid & 31, w = tid >> 5;
    int wm = w >> 2, wn = w & 3;
    int gid = lane >> 2, tig = lane & 3;
    int m0 = blockIdx.y * 128, n0 = blockIdx.x * BN;

    float acc[4][NF][4];
#pragma unroll
    for (int i = 0; i < 4; ++i)
#pragma unroll
        for (int j = 0; j < NF; ++j)
#pragma unroll
            for (int r = 0; r < 4; ++r) acc[i][j][r] = 0.f;

    int T = K >> 5;   // BK = 32 halves

    auto load_tile = [&](int t, int stg) {
        int k0 = t * 32;
#pragma unroll
        for (int it = 0; it < 2; ++it) {
            int idx = tid + it * 256;
            int row = idx >> 2, c = idx & 3;          // c: 16B chunk = 8 halves
            cp_async16(&As[stg][row * 20 + c * 4],
                       &A[(size_t)(m0 + row) * lda + k0 + c * 8]);
        }
#pragma unroll
        for (int it = 0; it < (BN * 4 + 255) / 256; ++it) {
            int idx = tid + it * 256;
            if (BN == 128 || idx < BN * 4) {
                int row = idx >> 2, c = idx & 3;
                cp_async16(&Bs[stg][row * 20 + c * 4],
                           &Bt[(size_t)(n0 + row) * ldb + k0 + c * 8]);
            }
        }
    };

    load_tile(0, 0); CP_COMMIT;
    for (int t = 0; t < T; ++t) {
        int cur = t & 1;
        if (t + 1 < T) { load_tile(t + 1, cur ^ 1); CP_COMMIT; CP_WAIT1; }
        else          { CP_WAIT0; }
        __syncthreads();
#pragma unroll
        for (int kk = 0; kk < 16; kk += 8) {          // uint units: 8 uints = 16 halves
            uint32_t a[4][4];
#pragma unroll
            for (int i = 0; i < 4; ++i) {
                int arow = wm * 64 + i * 16 + gid;
                a[i][0] = As[cur][arow * 20 + kk + tig];
                a[i][1] = As[cur][(arow + 8) * 20 + kk + tig];
                a[i][2] = As[cur][arow * 20 + kk + tig + 4];
                a[i][3] = As[cur][(arow + 8) * 20 + kk + tig + 4];
            }
            uint32_t b[NF][2];
#pragma unroll
            for (int j = 0; j < NF; ++j) {
                int brow = wn * WN + j * 8 + gid;
                b[j][0] = Bs[cur][brow * 20 + kk + tig];
                b[j][1] = Bs[cur][brow * 20 + kk + tig + 4];
            }
#pragma unroll
            for (int i = 0; i < 4; ++i)
#pragma unroll
                for (int j = 0; j < NF; ++j)
                    mma_f16(acc[i][j], a[i], b[j]);
        }
        __syncthreads();
    }

    // direct epilogue
#pragma unroll
    for (int i = 0; i < 4; ++i) {
        int r = m0 + wm * 64 + i * 16 + gid;
#pragma unroll
        for (int j = 0; j < NF; ++j) {
            int cgl = n0 + wn * WN + j * 8 + tig * 2;
            float x0 = acc[i][j][0] * scale, y0 = acc[i][j][1] * scale;
            float x1 = acc[i][j][2] * scale, y1 = acc[i][j][3] * scale;
            if (bias) {
                float bx = bias[cgl], by = bias[cgl + 1];
                x0 += bx; y0 += by; x1 += bx; y1 += by;
            }
            if (HALF_OUT) {
                __half* C = (__half*)Cv + coff;
                *(__half2*)&C[(size_t)r * ldc + cgl] = __floats2half2_rn(x0, y0);
                *(__half2*)&C[(size_t)(r + 8) * ldc + cgl] = __floats2half2_rn(x1, y1);
            } else {
                float* C = (float*)Cv + coff;
                *(float2*)&C[(size_t)r * ldc + cgl] = make_float2(x0, y0);
                *(float2*)&C[(size_t)(r + 8) * ldc + cgl] = make_float2(x1, y1);
            }
        }
    }
}

// ---------------------------------------------------------------------------
// Fused softmax + 8x8 head mix + BN. Reads S fp32, writes P fp16 to g_p.
// One block per (b,n); normalization folded into the mix.
// ---------------------------------------------------------------------------
__global__ __launch_bounds__(256)
void softmax_mix_kernel(const float* __restrict__ rw, const float* __restrict__ rb,
                        const float* __restrict__ gamma, const float* __restrict__ beta,
                        const float* __restrict__ mean, const float* __restrict__ var) {
    __shared__ float buf[8][1024];
    __shared__ float Wm[8][8];
    __shared__ float Cm[8];
    __shared__ float invsS[8];
    int tid = threadIdx.x;
    int bn = blockIdx.x;
    int b = bn >> 10, n = bn & 1023;

    if (tid < 64) {
        int h = tid >> 3, g = tid & 7;
        float inv = gamma[g] * rsqrtf(var[g] + 1e-3f);
        Wm[h][g] = rw[h * 8 + g] * inv;
        if (h == 0) Cm[g] = (rb[g] - mean[g]) * inv + beta[g];
    }

    size_t base = (size_t)b * 8388608 + (size_t)n * 1024;
    const float4* gin = (const float4*)(g_attn + base);
    float4* bf4 = (float4*)&buf[0][0];
#pragma unroll
    for (int i = 0; i < 8; ++i) {
        int idx = tid + i * 256;
        int h = idx >> 8, m4 = idx & 255;
        bf4[idx] = gin[(size_t)h * 262144 + m4];
    }
    __syncthreads();

    int w = tid >> 5, lane = tid & 31;
    float4* bw = (float4*)buf[w];
    float mx = -1e30f;
#pragma unroll
    for (int ii = 0; ii < 8; ++ii) {
        float4 p = bw[lane + ii * 32];
        mx = fmaxf(mx, fmaxf(fmaxf(p.x, p.y), fmaxf(p.z, p.w)));
    }
#pragma unroll
    for (int o = 16; o > 0; o >>= 1) mx = fmaxf(mx, __shfl_xor_sync(0xffffffffu, mx, o));
    float s = 0.f;
#pragma unroll
    for (int ii = 0; ii < 8; ++ii) {
        float4 p = bw[lane + ii * 32];
        p.x = __expf(p.x - mx); p.y = __expf(p.y - mx);
        p.z = __expf(p.z - mx); p.w = __expf(p.w - mx);
        bw[lane + ii * 32] = p;
        s += p.x + p.y + p.z + p.w;
    }
#pragma unroll
    for (int o = 16; o > 0; o >>= 1) s += __shfl_xor_sync(0xffffffffu, s, o);
    if (lane == 0) invsS[w] = 1.0f / s;
    __syncthreads();

    float4 p[8];
#pragma unroll
    for (int h = 0; h < 8; ++h) {
        float inv = invsS[h];
        float4 t = ((float4*)buf[h])[tid];
        p[h].x = t.x * inv; p[h].y = t.y * inv; p[h].z = t.z * inv; p[h].w = t.w * inv;
    }
    __half2* gout = (__half2*)(g_p + base);
#pragma unroll
    for (int g = 0; g < 8; ++g) {
        float c = Cm[g];
        float4 o = make_float4(c, c, c, c);
#pragma unroll
        for (int h = 0; h < 8; ++h) {
            float wv = Wm[h][g];
            o.x += p[h].x * wv; o.y += p[h].y * wv;
            o.z += p[h].z * wv; o.w += p[h].w * wv;
        }
        size_t h2base = (size_t)g * 524288 + tid * 2;
        gout[h2base]     = __floats2half2_rn(o.x, o.y);
        gout[h2base + 1] = __floats2half2_rn(o.z, o.w);
    }
}

// ---------------------------------------------------------------------------
extern "C" void kernel_launch(void* const* d_in, const int* in_sizes, int n_in,
                              void* d_out, int out_size) {
    const float* q      = (const float*)d_in[0];
    const float* k      = (const float*)d_in[1];
    const float* v      = (const float*)d_in[2];
    const float* conv_w = (const float*)d_in[3];
    const float* rw     = (const float*)d_in[4];
    const float* rb     = (const float*)d_in[5];
    const float* gamma  = (const float*)d_in[6];
    const float* beta   = (const float*)d_in[7];
    const float* mean   = (const float*)d_in[8];
    const float* var    = (const float*)d_in[9];
    const float* pw     = (const float*)d_in[10];
    const float* pb     = (const float*)d_in[11];
    float* out = (float*)d_out;

    float scale = 1.0f / sqrtf((float)HD_);

    __half *qh, *kh, *vh, *vt, *wt, *pp, *ctx;
    float *attn;
    cudaGetSymbolAddress((void**)&qh, g_qh);
    cudaGetSymbolAddress((void**)&kh, g_kh);
    cudaGetSymbolAddress((void**)&vh, g_vh);
    cudaGetSymbolAddress((void**)&vt, g_vt);
    cudaGetSymbolAddress((void**)&wt, g_wt);
    cudaGetSymbolAddress((void**)&attn, g_attn);
    cudaGetSymbolAddress((void**)&pp, g_p);
    cudaGetSymbolAddress((void**)&ctx, g_ctx);

    // 1. conv + head split (fp16 outputs)
    conv_heads_kernel<<<dim3(B_ * N_, 3), 256>>>(q, k, v, conv_w);

    // 2. transposes: V(half) -> (B,H,96,N) half, W(float) -> [n][k] half
    transpose_kernel<__half><<<dim3(HD_ / 32, N_ / 32, B_ * H_), dim3(32, 8)>>>(vh, vt, N_, HD_);
    transpose_kernel<float><<<dim3(DIM_ / 32, DIM_ / 32, 1), dim3(32, 8)>>>(pw, wt, DIM_, DIM_);

    // 3. QK^T (scaled) -> S fp32
    f16_gemm_nt<128, 32, false><<<dim3(N_ / 128, N_ / 128, B_ * H_), 256>>>(
        qh, kh, attn, HD_, HD_, HD_, N_,
        (long long)N_ * HD_, (long long)N_ * HD_,
        (long long)H_ * N_ * N_, (long long)N_ * N_,
        scale, nullptr);

    // 4. softmax + head mix + BN -> P fp16
    softmax_mix_kernel<<<B_ * N_, 256>>>(rw, rb, gamma, beta, mean, var);

    // 5. AV -> ctx (B,N,768) fp16
    f16_gemm_nt<96, 24, true><<<dim3(1, N_ / 128, B_ * H_), 256>>>(
        pp, vt, ctx, N_, N_, N_, DIM_,
        (long long)N_ * N_, (long long)HD_ * N_,
        (long long)N_ * DIM_, (long long)HD_,
        1.0f, nullptr);

    // 6. projection + bias -> out fp32
    f16_gemm_nt<128, 32, false><<<dim3(DIM_ / 128, (B_ * N_) / 128, 1), 256>>>(
        ctx, wt, out, DIM_, DIM_, DIM_, DIM_,
        0LL, 0LL, 0LL, 0LL,
        1.0f, pb);
}

// round 5
// speedup vs baseline: 4.1763x; 1.0348x over previous
#include <cuda_runtime.h>
#include <cuda_fp16.h>
#include <math.h>
#include <stdint.h>

// Problem constants
#define B_   8
#define N_   1024
#define DIM_ 768
#define H_   8
#define HD_  96

// ---------------- scratch (device globals; no allocation allowed) ----------
__device__ __align__(256) __half g_qh[B_*H_*N_*HD_];   // (B,H,N,96) fp16
__device__ __align__(256) __half g_kh[B_*H_*N_*HD_];
__device__ __align__(256) __half g_vh[B_*H_*N_*HD_];
__device__ __align__(256) __half g_vt[B_*H_*HD_*N_];   // (B,H,96,N) fp16
__device__ __align__(256) __half g_wt[DIM_*DIM_];      // proj W^T [n][k] fp16
__device__ __align__(256) __half g_s[67108864];        // S logits (B,H,N,N) fp16
__device__ __align__(256) __half g_p[67108864];        // P (post softmax+mix) fp16
__device__ __align__(256) __half g_ctx[B_*N_*DIM_];    // (B,N,768) fp16

// ---------------------------------------------------------------------------
__device__ __forceinline__ void mma_f16(float* c, const uint32_t* a, const uint32_t* b) {
    asm volatile(
        "mma.sync.aligned.m16n8k16.row.col.f32.f16.f16.f32 "
        "{%0,%1,%2,%3}, {%4,%5,%6,%7}, {%8,%9}, {%0,%1,%2,%3};"
        : "+f"(c[0]), "+f"(c[1]), "+f"(c[2]), "+f"(c[3])
        : "r"(a[0]), "r"(a[1]), "r"(a[2]), "r"(a[3]), "r"(b[0]), "r"(b[1]));
}
__device__ __forceinline__ void ldm_x4(uint32_t* r, uint32_t saddr) {
    asm volatile("ldmatrix.sync.aligned.m8n8.x4.shared.b16 {%0,%1,%2,%3}, [%4];"
        : "=r"(r[0]), "=r"(r[1]), "=r"(r[2]), "=r"(r[3]) : "r"(saddr));
}
__device__ __forceinline__ void ldm_x2(uint32_t* r, uint32_t saddr) {
    asm volatile("ldmatrix.sync.aligned.m8n8.x2.shared.b16 {%0,%1}, [%2];"
        : "=r"(r[0]), "=r"(r[1]) : "r"(saddr));
}
__device__ __forceinline__ void cp_async16(void* smem, const void* gmem) {
    uint32_t s = (uint32_t)__cvta_generic_to_shared(smem);
    asm volatile("cp.async.cg.shared.global [%0], [%1], 16;" :: "r"(s), "l"(gmem));
}
#define CP_COMMIT asm volatile("cp.async.commit_group;")
#define CP_WAIT1  asm volatile("cp.async.wait_group 1;")
#define CP_WAIT0  asm volatile("cp.async.wait_group 0;")

// ---------------------------------------------------------------------------
// Kernel 1: 3x3 SAME conv on 16x16x3 token image + head split -> fp16
// ---------------------------------------------------------------------------
__global__ void conv_heads_kernel(const float* __restrict__ q,
                                  const float* __restrict__ k,
                                  const float* __restrict__ v,
                                  const float* __restrict__ w) {
    __shared__ float img[768];
    __shared__ float wt[81];
    int token = blockIdx.x;
    int which = blockIdx.y;
    int tid = threadIdx.x;

    const float* src = (which == 0) ? q : (which == 1) ? k : v;
    __half* dst = (which == 0) ? g_qh : (which == 1) ? g_kh : g_vh;

    const float* xp = src + (size_t)token * DIM_;
    for (int i = tid; i < 768; i += 256) img[i] = xp[i];
    if (tid < 81) wt[tid] = w[tid];
    __syncthreads();

    int s = tid >> 4, t = tid & 15;
    float acc0 = 0.f, acc1 = 0.f, acc2 = 0.f;
#pragma unroll
    for (int dy = 0; dy < 3; ++dy) {
        int ys = s + dy - 1;
        bool vy = ((unsigned)ys < 16u);
#pragma unroll
        for (int dx = 0; dx < 3; ++dx) {
            int xs = t + dx - 1;
            if (vy && ((unsigned)xs < 16u)) {
                int base = (ys * 16 + xs) * 3;
                int wb = (dy * 3 + dx) * 9;
#pragma unroll
                for (int ci = 0; ci < 3; ++ci) {
                    float pv = img[base + ci];
                    acc0 += pv * wt[wb + ci * 3 + 0];
                    acc1 += pv * wt[wb + ci * 3 + 1];
                    acc2 += pv * wt[wb + ci * 3 + 2];
                }
            }
        }
    }
    int b = token >> 10, n = token & 1023;
    float accs[3] = {acc0, acc1, acc2};
    int p = tid * 3;
#pragma unroll
    for (int co = 0; co < 3; ++co) {
        int pp = p + co;
        int h = pp / 96;
        int d = pp - h * 96;
        dst[(((size_t)b * H_ + h) * N_ + n) * HD_ + d] = __float2half_rn(accs[co]);
    }
}

// ---------------------------------------------------------------------------
// Kernel 2: batched tiled transpose: (batch,R,C) -> (batch,C,R), TI -> half
// ---------------------------------------------------------------------------
template<typename TI>
__global__ void transpose_kernel(const TI* __restrict__ in, __half* __restrict__ out,
                                 int R, int C) {
    __shared__ float t[32][33];
    int c0 = blockIdx.x * 32, r0 = blockIdx.y * 32;
    const TI* ip = in + (size_t)blockIdx.z * R * C;
    __half* op = out + (size_t)blockIdx.z * R * C;
    int x = threadIdx.x, y = threadIdx.y;
#pragma unroll
    for (int i = 0; i < 32; i += 8)
        t[y + i][x] = (float)ip[(size_t)(r0 + y + i) * C + c0 + x];
    __syncthreads();
#pragma unroll
    for (int i = 0; i < 32; i += 8)
        op[(size_t)(c0 + y + i) * R + r0 + x] = __float2half_rn(t[x][y + i]);
}

// ---------------------------------------------------------------------------
// FP16 NT GEMM (fp32 accum), cp.async double-buffered, ldmatrix fragments.
// C[m][n] = scale * sum_k A[m][k]*Bt[n][k] (+ bias[n]).
// BM=128, BK=32 halves, BN in {128,96}. 256 thr = 8 warps (2x4), warp 64xWN.
// Smem rows stride 20 uints (80B) -> conflict-free for ldmatrix.
// ---------------------------------------------------------------------------
template<int BN, int WN, bool HALF_OUT>
__global__ __launch_bounds__(256)
void f16_gemm_nt(const __half* __restrict__ A, const __half* __restrict__ Bt,
                 void* __restrict__ Cv,
                 int K, int lda, int ldb, int ldc,
                 long long sA, long long sB, long long sCo, long long sCi,
                 float scale, const float* __restrict__ bias) {
    constexpr int NF = WN / 8;
    __shared__ __align__(16) uint32_t As[2][128 * 20];
    __shared__ __align__(16) uint32_t Bs[2][BN * 20];

    int z = blockIdx.z;
    A += (size_t)z * sA;
    Bt += (size_t)z * sB;
    size_t coff = (size_t)(z >> 3) * sCo + (size_t)(z & 7) * sCi;

    int tid = threadIdx.x;
    int lane = tid & 31, w = tid >> 5;
    int wm = w >> 2, wn = w & 3;
    int gid = lane >> 2, tig = lane & 3;
    int m0 = blockIdx.y * 128, n0 = blockIdx.x * BN;

    // per-lane ldmatrix offsets (bytes within tile)
    int lt = lane >> 3, lr = lane & 7;
    int a_lane_off = ((lt & 1) * 8 + lr) * 80 + (lt >> 1) * 16;
    int b_lane_off = ((lt >> 1) * 8 + lr) * 80 + (lt & 1) * 16;
    int b2_lane_off = (lane & 7) * 80 + ((lane >> 3) & 1) * 16;

    float acc[4][NF][4];
#pragma unroll
    for (int i = 0; i < 4; ++i)
#pragma unroll
        for (int j = 0; j < NF; ++j)
#pragma unroll
            for (int r = 0; r < 4; ++r) acc[i][j][r] = 0.f;

    int T = K >> 5;   // BK = 32 halves

    auto load_tile = [&](int t, int stg) {
        int k0 = t * 32;
#pragma unroll
        for (int it = 0; it < 2; ++it) {
            int idx = tid + it * 256;
            int row = idx >> 2, c = idx & 3;
            cp_async16(&As[stg][row * 20 + c * 4],
                       &A[(size_t)(m0 + row) * lda + k0 + c * 8]);
        }
#pragma unroll
        for (int it = 0; it < (BN * 4 + 255) / 256; ++it) {
            int idx = tid + it * 256;
            if (BN == 128 || idx < BN * 4) {
                int row = idx >> 2, c = idx & 3;
                cp_async16(&Bs[stg][row * 20 + c * 4],
                           &Bt[(size_t)(n0 + row) * ldb + k0 + c * 8]);
            }
        }
    };

    load_tile(0, 0); CP_COMMIT;
    for (int t = 0; t < T; ++t) {
        int cur = t & 1;
        if (t + 1 < T) { load_tile(t + 1, cur ^ 1); CP_COMMIT; CP_WAIT1; }
        else          { CP_WAIT0; }
        __syncthreads();

        uint32_t abase = (uint32_t)__cvta_generic_to_shared(&As[cur][0]);
        uint32_t bbase = (uint32_t)__cvta_generic_to_shared(&Bs[cur][0]);
#pragma unroll
        for (int kk = 0; kk < 16; kk += 8) {   // 2 k-groups of 16 halves
            int kk4 = kk * 4;
            uint32_t a[4][4];
#pragma unroll
            for (int i = 0; i < 4; ++i)
                ldm_x4(a[i], abase + (wm * 64 + i * 16) * 80 + kk4 + a_lane_off);
            uint32_t bf[NF * 2];
#pragma unroll
            for (int p = 0; p < NF / 2; ++p)
                ldm_x4(&bf[p * 4], bbase + (wn * WN + p * 16) * 80 + kk4 + b_lane_off);
            if (NF & 1)
                ldm_x2(&bf[(NF - 1) * 2],
                       bbase + (wn * WN + (NF - 1) * 8) * 80 + kk4 + b2_lane_off);
#pragma unroll
            for (int i = 0; i < 4; ++i)
#pragma unroll
                for (int j = 0; j < NF; ++j)
                    mma_f16(acc[i][j], a[i], &bf[j * 2]);
        }
        __syncthreads();
    }

    // direct epilogue
#pragma unroll
    for (int i = 0; i < 4; ++i) {
        int r = m0 + wm * 64 + i * 16 + gid;
#pragma unroll
        for (int j = 0; j < NF; ++j) {
            int cgl = n0 + wn * WN + j * 8 + tig * 2;
            float x0 = acc[i][j][0] * scale, y0 = acc[i][j][1] * scale;
            float x1 = acc[i][j][2] * scale, y1 = acc[i][j][3] * scale;
            if (bias) {
                float bx = bias[cgl], by = bias[cgl + 1];
                x0 += bx; y0 += by; x1 += bx; y1 += by;
            }
            if (HALF_OUT) {
                __half* C = (__half*)Cv + coff;
                *(__half2*)&C[(size_t)r * ldc + cgl] = __floats2half2_rn(x0, y0);
                *(__half2*)&C[(size_t)(r + 8) * ldc + cgl] = __floats2half2_rn(x1, y1);
            } else {
                float* C = (float*)Cv + coff;
                *(float2*)&C[(size_t)r * ldc + cgl] = make_float2(x0, y0);
                *(float2*)&C[(size_t)(r + 8) * ldc + cgl] = make_float2(x1, y1);
            }
        }
    }
}

// ---------------------------------------------------------------------------
// Fused softmax + 8x8 head mix + BN. Reads S fp16, writes P fp16.
// One block per (b,n); normalization folded into the mix.
// ---------------------------------------------------------------------------
__global__ __launch_bounds__(256)
void softmax_mix_kernel(const float* __restrict__ rw, const float* __restrict__ rb,
                        const float* __restrict__ gamma, const float* __restrict__ beta,
                        const float* __restrict__ mean, const float* __restrict__ var) {
    __shared__ float buf[8][1024];
    __shared__ float Wm[8][8];
    __shared__ float Cm[8];
    __shared__ float invsS[8];
    int tid = threadIdx.x;
    int bn = blockIdx.x;
    int b = bn >> 10, n = bn & 1023;

    if (tid < 64) {
        int h = tid >> 3, g = tid & 7;
        float inv = gamma[g] * rsqrtf(var[g] + 1e-3f);
        Wm[h][g] = rw[h * 8 + g] * inv;
        if (h == 0) Cm[g] = (rb[g] - mean[g]) * inv + beta[g];
    }

    size_t base = (size_t)b * 8388608 + (size_t)n * 1024;
    const uint4* gin = (const uint4*)(g_s + base);   // 8 halves per uint4
#pragma unroll
    for (int i = 0; i < 4; ++i) {
        int idx = tid + i * 256;                     // 0..1023
        int h = idx >> 7, m8 = idx & 127;
        uint4 u = gin[(size_t)h * 131072 + m8];
        const __half2* hp = (const __half2*)&u;
        float* bp = &buf[h][m8 * 8];
#pragma unroll
        for (int jj = 0; jj < 4; ++jj) {
            float2 f = __half22float2(hp[jj]);
            bp[jj * 2] = f.x; bp[jj * 2 + 1] = f.y;
        }
    }
    __syncthreads();

    int w = tid >> 5, lane = tid & 31;
    float4* bw = (float4*)buf[w];
    float mx = -1e30f;
#pragma unroll
    for (int ii = 0; ii < 8; ++ii) {
        float4 p = bw[lane + ii * 32];
        mx = fmaxf(mx, fmaxf(fmaxf(p.x, p.y), fmaxf(p.z, p.w)));
    }
#pragma unroll
    for (int o = 16; o > 0; o >>= 1) mx = fmaxf(mx, __shfl_xor_sync(0xffffffffu, mx, o));
    float s = 0.f;
#pragma unroll
    for (int ii = 0; ii < 8; ++ii) {
        float4 p = bw[lane + ii * 32];
        p.x = __expf(p.x - mx); p.y = __expf(p.y - mx);
        p.z = __expf(p.z - mx); p.w = __expf(p.w - mx);
        bw[lane + ii * 32] = p;
        s += p.x + p.y + p.z + p.w;
    }
#pragma unroll
    for (int o = 16; o > 0; o >>= 1) s += __shfl_xor_sync(0xffffffffu, s, o);
    if (lane == 0) invsS[w] = 1.0f / s;
    __syncthreads();

    float4 p[8];
#pragma unroll
    for (int h = 0; h < 8; ++h) {
        float inv = invsS[h];
        float4 t = ((float4*)buf[h])[tid];
        p[h].x = t.x * inv; p[h].y = t.y * inv; p[h].z = t.z * inv; p[h].w = t.w * inv;
    }
    __half2* gout = (__half2*)(g_p + base);
#pragma unroll
    for (int g = 0; g < 8; ++g) {
        float c = Cm[g];
        float4 o = make_float4(c, c, c, c);
#pragma unroll
        for (int h = 0; h < 8; ++h) {
            float wv = Wm[h][g];
            o.x += p[h].x * wv; o.y += p[h].y * wv;
            o.z += p[h].z * wv; o.w += p[h].w * wv;
        }
        size_t h2base = (size_t)g * 524288 + tid * 2;
        gout[h2base]     = __floats2half2_rn(o.x, o.y);
        gout[h2base + 1] = __floats2half2_rn(o.z, o.w);
    }
}

// ---------------------------------------------------------------------------
extern "C" void kernel_launch(void* const* d_in, const int* in_sizes, int n_in,
                              void* d_out, int out_size) {
    const float* q      = (const float*)d_in[0];
    const float* k      = (const float*)d_in[1];
    const float* v      = (const float*)d_in[2];
    const float* conv_w = (const float*)d_in[3];
    const float* rw     = (const float*)d_in[4];
    const float* rb     = (const float*)d_in[5];
    const float* gamma  = (const float*)d_in[6];
    const float* beta   = (const float*)d_in[7];
    const float* mean   = (const float*)d_in[8];
    const float* var    = (const float*)d_in[9];
    const float* pw     = (const float*)d_in[10];
    const float* pb     = (const float*)d_in[11];
    float* out = (float*)d_out;

    float scale = 1.0f / sqrtf((float)HD_);

    __half *qh, *kh, *vh, *vt, *wt, *sS, *pp, *ctx;
    cudaGetSymbolAddress((void**)&qh, g_qh);
    cudaGetSymbolAddress((void**)&kh, g_kh);
    cudaGetSymbolAddress((void**)&vh, g_vh);
    cudaGetSymbolAddress((void**)&vt, g_vt);
    cudaGetSymbolAddress((void**)&wt, g_wt);
    cudaGetSymbolAddress((void**)&sS, g_s);
    cudaGetSymbolAddress((void**)&pp, g_p);
    cudaGetSymbolAddress((void**)&ctx, g_ctx);

    // 1. conv + head split (fp16 outputs)
    conv_heads_kernel<<<dim3(B_ * N_, 3), 256>>>(q, k, v, conv_w);

    // 2. transposes: V(half) -> (B,H,96,N) half, W(float) -> [n][k] half
    transpose_kernel<__half><<<dim3(HD_ / 32, N_ / 32, B_ * H_), dim3(32, 8)>>>(vh, vt, N_, HD_);
    transpose_kernel<float><<<dim3(DIM_ / 32, DIM_ / 32, 1), dim3(32, 8)>>>(pw, wt, DIM_, DIM_);

    // 3. QK^T (scaled) -> S fp16
    f16_gemm_nt<128, 32, true><<<dim3(N_ / 128, N_ / 128, B_ * H_), 256>>>(
        qh, kh, sS, HD_, HD_, HD_, N_,
        (long long)N_ * HD_, (long long)N_ * HD_,
        (long long)H_ * N_ * N_, (long long)N_ * N_,
        scale, nullptr);

    // 4. softmax + head mix + BN -> P fp16
    softmax_mix_kernel<<<B_ * N_, 256>>>(rw, rb, gamma, beta, mean, var);

    // 5. AV -> ctx (B,N,768) fp16
    f16_gemm_nt<96, 24, true><<<dim3(1, N_ / 128, B_ * H_), 256>>>(
        pp, vt, ctx, N_, N_, N_, DIM_,
        (long long)N_ * N_, (long long)HD_ * N_,
        (long long)N_ * DIM_, (long long)HD_,
        1.0f, nullptr);

    // 6. projection + bias -> out fp32
    f16_gemm_nt<128, 32, false><<<dim3(DIM_ / 128, (B_ * N_) / 128, 1), 256>>>(
        ctx, wt, out, DIM_, DIM_, DIM_, DIM_,
        0LL, 0LL, 0LL, 0LL,
        1.0f, pb);
}

// round 7
// speedup vs baseline: 4.4056x; 1.0549x over previous
#include <cuda_runtime.h>
#include <cuda_fp16.h>
#include <math.h>
#include <stdint.h>

// Problem constants
#define B_   8
#define N_   1024
#define DIM_ 768
#define H_   8
#define HD_  96

// ---------------- scratch (device globals; no allocation allowed) ----------
__device__ __align__(256) __half g_qh[B_*H_*N_*HD_];   // (B,H,N,96) fp16
__device__ __align__(256) __half g_kh[B_*H_*N_*HD_];
__device__ __align__(256) __half g_vh[B_*H_*N_*HD_];
__device__ __align__(256) __half g_vt[B_*H_*HD_*N_];   // (B,H,96,N) fp16
__device__ __align__(256) __half g_wt[DIM_*DIM_];      // proj W^T [n][k] fp16
__device__ __align__(256) __half g_s[67108864];        // S logits (B,H,N,N) fp16
__device__ __align__(256) __half g_p[67108864];        // P (post softmax+mix) fp16
__device__ __align__(256) __half g_ctx[B_*N_*DIM_];    // (B,N,768) fp16

// ---------------------------------------------------------------------------
__device__ __forceinline__ void mma_f16(float* c, const uint32_t* a, const uint32_t* b) {
    asm volatile(
        "mma.sync.aligned.m16n8k16.row.col.f32.f16.f16.f32 "
        "{%0,%1,%2,%3}, {%4,%5,%6,%7}, {%8,%9}, {%0,%1,%2,%3};"
        : "+f"(c[0]), "+f"(c[1]), "+f"(c[2]), "+f"(c[3])
        : "r"(a[0]), "r"(a[1]), "r"(a[2]), "r"(a[3]), "r"(b[0]), "r"(b[1]));
}
__device__ __forceinline__ void ldm_x4(uint32_t* r, uint32_t saddr) {
    asm volatile("ldmatrix.sync.aligned.m8n8.x4.shared.b16 {%0,%1,%2,%3}, [%4];"
        : "=r"(r[0]), "=r"(r[1]), "=r"(r[2]), "=r"(r[3]) : "r"(saddr));
}
__device__ __forceinline__ void cp_async16(void* smem, const void* gmem) {
    uint32_t s = (uint32_t)__cvta_generic_to_shared(smem);
    asm volatile("cp.async.cg.shared.global [%0], [%1], 16;" :: "r"(s), "l"(gmem));
}
#define CP_COMMIT asm volatile("cp.async.commit_group;")
#define CP_WAIT1  asm volatile("cp.async.wait_group 1;")
#define CP_WAIT0  asm volatile("cp.async.wait_group 0;")

// ---------------------------------------------------------------------------
// Kernel 1: 3x3 SAME conv on 16x16x3 token image + head split -> fp16
// ---------------------------------------------------------------------------
__global__ void conv_heads_kernel(const float* __restrict__ q,
                                  const float* __restrict__ k,
                                  const float* __restrict__ v,
                                  const float* __restrict__ w) {
    __shared__ float img[768];
    __shared__ float wt[81];
    int token = blockIdx.x;
    int which = blockIdx.y;
    int tid = threadIdx.x;

    const float* src = (which == 0) ? q : (which == 1) ? k : v;
    __half* dst = (which == 0) ? g_qh : (which == 1) ? g_kh : g_vh;

    const float* xp = src + (size_t)token * DIM_;
    for (int i = tid; i < 768; i += 256) img[i] = xp[i];
    if (tid < 81) wt[tid] = w[tid];
    __syncthreads();

    int s = tid >> 4, t = tid & 15;
    float acc0 = 0.f, acc1 = 0.f, acc2 = 0.f;
#pragma unroll
    for (int dy = 0; dy < 3; ++dy) {
        int ys = s + dy - 1;
        bool vy = ((unsigned)ys < 16u);
#pragma unroll
        for (int dx = 0; dx < 3; ++dx) {
            int xs = t + dx - 1;
            if (vy && ((unsigned)xs < 16u)) {
                int base = (ys * 16 + xs) * 3;
                int wb = (dy * 3 + dx) * 9;
#pragma unroll
                for (int ci = 0; ci < 3; ++ci) {
                    float pv = img[base + ci];
                    acc0 += pv * wt[wb + ci * 3 + 0];
                    acc1 += pv * wt[wb + ci * 3 + 1];
                    acc2 += pv * wt[wb + ci * 3 + 2];
                }
            }
        }
    }
    int b = token >> 10, n = token & 1023;
    float accs[3] = {acc0, acc1, acc2};
    int p = tid * 3;
#pragma unroll
    for (int co = 0; co < 3; ++co) {
        int pp = p + co;
        int h = pp / 96;
        int d = pp - h * 96;
        dst[(((size_t)b * H_ + h) * N_ + n) * HD_ + d] = __float2half_rn(accs[co]);
    }
}

// ---------------------------------------------------------------------------
// Kernel 2: batched tiled transpose: (batch,R,C) -> (batch,C,R), TI -> half
// ---------------------------------------------------------------------------
template<typename TI>
__global__ void transpose_kernel(const TI* __restrict__ in, __half* __restrict__ out,
                                 int R, int C) {
    __shared__ float t[32][33];
    int c0 = blockIdx.x * 32, r0 = blockIdx.y * 32;
    const TI* ip = in + (size_t)blockIdx.z * R * C;
    __half* op = out + (size_t)blockIdx.z * R * C;
    int x = threadIdx.x, y = threadIdx.y;
#pragma unroll
    for (int i = 0; i < 32; i += 8)
        t[y + i][x] = (float)ip[(size_t)(r0 + y + i) * C + c0 + x];
    __syncthreads();
#pragma unroll
    for (int i = 0; i < 32; i += 8)
        op[(size_t)(c0 + y + i) * R + r0 + x] = __float2half_rn(t[x][y + i]);
}

// ---------------------------------------------------------------------------
// FP16 NT GEMM (fp32 accum), cp.async double-buffered, ldmatrix fragments.
// C[m][n] = scale * sum_k A[m][k]*Bt[n][k] (+ bias[n]).
// 128 threads = 4 warps (2x2). CTA tile 128 x BN, warp tile 64 x WN (WN=BN/2).
// BK=32 halves. Smem rows stride 20 uints (80B) -> conflict-free ldmatrix.
// ---------------------------------------------------------------------------
template<int BN, bool HALF_OUT>
__global__ __launch_bounds__(128, 2)
void f16_gemm_nt(const __half* __restrict__ A, const __half* __restrict__ Bt,
                 void* __restrict__ Cv,
                 int K, int lda, int ldb, int ldc,
                 long long sA, long long sB, long long sCo, long long sCi,
                 float scale, const float* __restrict__ bias) {
    constexpr int WN = BN / 2;
    constexpr int NF = WN / 8;              // 8 (BN=128) or 6 (BN=96)
    __shared__ __align__(16) uint32_t As[2][128 * 20];
    __shared__ __align__(16) uint32_t Bs[2][BN * 20];

    int z = blockIdx.z;
    A += (size_t)z * sA;
    Bt += (size_t)z * sB;
    size_t coff = (size_t)(z >> 3) * sCo + (size_t)(z & 7) * sCi;

    int tid = threadIdx.x;
    int lane = tid & 31, w = tid >> 5;
    int wm = w >> 1, wn = w & 1;
    int gid = lane >> 2, tig = lane & 3;
    int m0 = blockIdx.y * 128, n0 = blockIdx.x * BN;

    // per-lane ldmatrix offsets (bytes within tile)
    int lt = lane >> 3, lr = lane & 7;
    int a_lane_off = ((lt & 1) * 8 + lr) * 80 + (lt >> 1) * 16;
    int b_lane_off = ((lt >> 1) * 8 + lr) * 80 + (lt & 1) * 16;

    float acc[4][NF][4];
#pragma unroll
    for (int i = 0; i < 4; ++i)
#pragma unroll
        for (int j = 0; j < NF; ++j)
#pragma unroll
            for (int r = 0; r < 4; ++r) acc[i][j][r] = 0.f;

    int T = K >> 5;   // BK = 32 halves

    auto load_tile = [&](int t, int stg) {
        int k0 = t * 32;
#pragma unroll
        for (int it = 0; it < 4; ++it) {
            int idx = tid + it * 128;
            int row = idx >> 2, c = idx & 3;          // c: 16B chunk = 8 halves
            cp_async16(&As[stg][row * 20 + c * 4],
                       &A[(size_t)(m0 + row) * lda + k0 + c * 8]);
        }
#pragma unroll
        for (int it = 0; it < (BN * 4 + 127) / 128; ++it) {
            int idx = tid + it * 128;
            if (BN == 128 || idx < BN * 4) {
                int row = idx >> 2, c = idx & 3;
                cp_async16(&Bs[stg][row * 20 + c * 4],
                           &Bt[(size_t)(n0 + row) * ldb + k0 + c * 8]);
            }
        }
    };

    load_tile(0, 0); CP_COMMIT;
    for (int t = 0; t < T; ++t) {
        int cur = t & 1;
        if (t + 1 < T) { load_tile(t + 1, cur ^ 1); CP_COMMIT; CP_WAIT1; }
        else          { CP_WAIT0; }
        __syncthreads();

        uint32_t abase = (uint32_t)__cvta_generic_to_shared(&As[cur][0]);
        uint32_t bbase = (uint32_t)__cvta_generic_to_shared(&Bs[cur][0]);
#pragma unroll
        for (int kk = 0; kk < 16; kk += 8) {   // 2 k-groups of 16 halves
            int kk4 = kk * 4;
            uint32_t a[4][4];
#pragma unroll
            for (int i = 0; i < 4; ++i)
                ldm_x4(a[i], abase + (wm * 64 + i * 16) * 80 + kk4 + a_lane_off);
            uint32_t bf[NF * 2];
#pragma unroll
            for (int p = 0; p < NF / 2; ++p)
                ldm_x4(&bf[p * 4], bbase + (wn * WN + p * 16) * 80 + kk4 + b_lane_off);
#pragma unroll
            for (int i = 0; i < 4; ++i)
#pragma unroll
                for (int j = 0; j < NF; ++j)
                    mma_f16(acc[i][j], a[i], &bf[j * 2]);
        }
        __syncthreads();
    }

    // direct epilogue
#pragma unroll
    for (int i = 0; i < 4; ++i) {
        int r = m0 + wm * 64 + i * 16 + gid;
#pragma unroll
        for (int j = 0; j < NF; ++j) {
            int cgl = n0 + wn * WN + j * 8 + tig * 2;
            float x0 = acc[i][j][0] * scale, y0 = acc[i][j][1] * scale;
            float x1 = acc[i][j][2] * scale, y1 = acc[i][j][3] * scale;
            if (bias) {
                float bx = bias[cgl], by = bias[cgl + 1];
                x0 += bx; y0 += by; x1 += bx; y1 += by;
            }
            if (HALF_OUT) {
                __half* C = (__half*)Cv + coff;
                *(__half2*)&C[(size_t)r * ldc + cgl] = __floats2half2_rn(x0, y0);
                *(__half2*)&C[(size_t)(r + 8) * ldc + cgl] = __floats2half2_rn(x1, y1);
            } else {
                float* C = (float*)Cv + coff;
                *(float2*)&C[(size_t)r * ldc + cgl] = make_float2(x0, y0);
                *(float2*)&C[(size_t)(r + 8) * ldc + cgl] = make_float2(x1, y1);
            }
        }
    }
}

// ---------------------------------------------------------------------------
// Fused softmax + 8x8 head mix + BN. Reads S fp16, writes P fp16.
// One block per (b,n); normalization folded into the mix.
// ---------------------------------------------------------------------------
__global__ __launch_bounds__(256)
void softmax_mix_kernel(const float* __restrict__ rw, const float* __restrict__ rb,
                        const float* __restrict__ gamma, const float* __restrict__ beta,
                        const float* __restrict__ mean, const float* __restrict__ var) {
    __shared__ float buf[8][1024];
    __shared__ float Wm[8][8];
    __shared__ float Cm[8];
    __shared__ float invsS[8];
    int tid = threadIdx.x;
    int bn = blockIdx.x;
    int b = bn >> 10, n = bn & 1023;

    if (tid < 64) {
        int h = tid >> 3, g = tid & 7;
        float inv = gamma[g] * rsqrtf(var[g] + 1e-3f);
        Wm[h][g] = rw[h * 8 + g] * inv;
        if (h == 0) Cm[g] = (rb[g] - mean[g]) * inv + beta[g];
    }

    size_t base = (size_t)b * 8388608 + (size_t)n * 1024;
    const uint4* gin = (const uint4*)(g_s + base);   // 8 halves per uint4
#pragma unroll
    for (int i = 0; i < 4; ++i) {
        int idx = tid + i * 256;                     // 0..1023
        int h = idx >> 7, m8 = idx & 127;
        uint4 u = gin[(size_t)h * 131072 + m8];
        const __half2* hp = (const __half2*)&u;
        float* bp = &buf[h][m8 * 8];
#pragma unroll
        for (int jj = 0; jj < 4; ++jj) {
            float2 f = __half22float2(hp[jj]);
            bp[jj * 2] = f.x; bp[jj * 2 + 1] = f.y;
        }
    }
    __syncthreads();

    int w = tid >> 5, lane = tid & 31;
    float4* bw = (float4*)buf[w];
    float mx = -1e30f;
#pragma unroll
    for (int ii = 0; ii < 8; ++ii) {
        float4 p = bw[lane + ii * 32];
        mx = fmaxf(mx, fmaxf(fmaxf(p.x, p.y), fmaxf(p.z, p.w)));
    }
#pragma unroll
    for (int o = 16; o > 0; o >>= 1) mx = fmaxf(mx, __shfl_xor_sync(0xffffffffu, mx, o));
    float s = 0.f;
#pragma unroll
    for (int ii = 0; ii < 8; ++ii) {
        float4 p = bw[lane + ii * 32];
        p.x = __expf(p.x - mx); p.y = __expf(p.y - mx);
        p.z = __expf(p.z - mx); p.w = __expf(p.w - mx);
        bw[lane + ii * 32] = p;
        s += p.x + p.y + p.z + p.w;
    }
#pragma unroll
    for (int o = 16; o > 0; o >>= 1) s += __shfl_xor_sync(0xffffffffu, s, o);
    if (lane == 0) invsS[w] = 1.0f / s;
    __syncthreads();

    float4 p[8];
#pragma unroll
    for (int h = 0; h < 8; ++h) {
        float inv = invsS[h];
        float4 t = ((float4*)buf[h])[tid];
        p[h].x = t.x * inv; p[h].y = t.y * inv; p[h].z = t.z * inv; p[h].w = t.w * inv;
    }
    __half2* gout = (__half2*)(g_p + base);
#pragma unroll
    for (int g = 0; g < 8; ++g) {
        float c = Cm[g];
        float4 o = make_float4(c, c, c, c);
#pragma unroll
        for (int h = 0; h < 8; ++h) {
            float wv = Wm[h][g];
            o.x += p[h].x * wv; o.y += p[h].y * wv;
            o.z += p[h].z * wv; o.w += p[h].w * wv;
        }
        size_t h2base = (size_t)g * 524288 + tid * 2;
        gout[h2base]     = __floats2half2_rn(o.x, o.y);
        gout[h2base + 1] = __floats2half2_rn(o.z, o.w);
    }
}

// ---------------------------------------------------------------------------
extern "C" void kernel_launch(void* const* d_in, const int* in_sizes, int n_in,
                              void* d_out, int out_size) {
    const float* q      = (const float*)d_in[0];
    const float* k      = (const float*)d_in[1];
    const float* v      = (const float*)d_in[2];
    const float* conv_w = (const float*)d_in[3];
    const float* rw     = (const float*)d_in[4];
    const float* rb     = (const float*)d_in[5];
    const float* gamma  = (const float*)d_in[6];
    const float* beta   = (const float*)d_in[7];
    const float* mean   = (const float*)d_in[8];
    const float* var    = (const float*)d_in[9];
    const float* pw     = (const float*)d_in[10];
    const float* pb     = (const float*)d_in[11];
    float* out = (float*)d_out;

    float scale = 1.0f / sqrtf((float)HD_);

    __half *qh, *kh, *vh, *vt, *wt, *sS, *pp, *ctx;
    cudaGetSymbolAddress((void**)&qh, g_qh);
    cudaGetSymbolAddress((void**)&kh, g_kh);
    cudaGetSymbolAddress((void**)&vh, g_vh);
    cudaGetSymbolAddress((void**)&vt, g_vt);
    cudaGetSymbolAddress((void**)&wt, g_wt);
    cudaGetSymbolAddress((void**)&sS, g_s);
    cudaGetSymbolAddress((void**)&pp, g_p);
    cudaGetSymbolAddress((void**)&ctx, g_ctx);

    // 1. conv + head split (fp16 outputs)
    conv_heads_kernel<<<dim3(B_ * N_, 3), 256>>>(q, k, v, conv_w);

    // 2. transposes: V(half) -> (B,H,96,N) half, W(float) -> [n][k] half
    transpose_kernel<__half><<<dim3(HD_ / 32, N_ / 32, B_ * H_), dim3(32, 8)>>>(vh, vt, N_, HD_);
    transpose_kernel<float><<<dim3(DIM_ / 32, DIM_ / 32, 1), dim3(32, 8)>>>(pw, wt, DIM_, DIM_);

    // 3. QK^T (scaled) -> S fp16
    f16_gemm_nt<128, true><<<dim3(N_ / 128, N_ / 128, B_ * H_), 128>>>(
        qh, kh, sS, HD_, HD_, HD_, N_,
        (long long)N_ * HD_, (long long)N_ * HD_,
        (long long)H_ * N_ * N_, (long long)N_ * N_,
        scale, nullptr);

    // 4. softmax + head mix + BN -> P fp16
    softmax_mix_kernel<<<B_ * N_, 256>>>(rw, rb, gamma, beta, mean, var);

    // 5. AV -> ctx (B,N,768) fp16
    f16_gemm_nt<96, true><<<dim3(1, N_ / 128, B_ * H_), 128>>>(
        pp, vt, ctx, N_, N_, N_, DIM_,
        (long long)N_ * N_, (long long)HD_ * N_,
        (long long)N_ * DIM_, (long long)HD_,
        1.0f, nullptr);

    // 6. projection + bias -> out fp32
    f16_gemm_nt<128, false><<<dim3(DIM_ / 128, (B_ * N_) / 128, 1), 128>>>(
        ctx, wt, out, DIM_, DIM_, DIM_, DIM_,
        0LL, 0LL, 0LL, 0LL,
        1.0f, pb);
}

// round 8
// speedup vs baseline: 4.6953x; 1.0658x over previous
#include <cuda_runtime.h>
#include <cuda_fp16.h>
#include <math.h>
#include <stdint.h>

// Problem constants
#define B_   8
#define N_   1024
#define DIM_ 768
#define H_   8
#define HD_  96

// ---------------- scratch (device globals; no allocation allowed) ----------
__device__ __align__(256) __half g_qh[B_*H_*N_*HD_];   // (B,H,N,96) fp16
__device__ __align__(256) __half g_kh[B_*H_*N_*HD_];
__device__ __align__(256) __half g_vh[B_*H_*N_*HD_];
__device__ __align__(256) __half g_vt[B_*H_*HD_*N_];   // (B,H,96,N) fp16
__device__ __align__(256) __half g_wt[DIM_*DIM_];      // proj W^T [n][k] fp16
__device__ __align__(256) __half g_s[67108864];        // S logits (B,H,N,N) fp16
__device__ __align__(256) __half g_p[67108864];        // P (post softmax+mix) fp16
__device__ __align__(256) __half g_ctx[B_*N_*DIM_];    // (B,N,768) fp16

// ---------------------------------------------------------------------------
__device__ __forceinline__ void mma_f16(float* c, const uint32_t* a, const uint32_t* b) {
    asm volatile(
        "mma.sync.aligned.m16n8k16.row.col.f32.f16.f16.f32 "
        "{%0,%1,%2,%3}, {%4,%5,%6,%7}, {%8,%9}, {%0,%1,%2,%3};"
        : "+f"(c[0]), "+f"(c[1]), "+f"(c[2]), "+f"(c[3])
        : "r"(a[0]), "r"(a[1]), "r"(a[2]), "r"(a[3]), "r"(b[0]), "r"(b[1]));
}
__device__ __forceinline__ void ldm_x4(uint32_t* r, uint32_t saddr) {
    asm volatile("ldmatrix.sync.aligned.m8n8.x4.shared.b16 {%0,%1,%2,%3}, [%4];"
        : "=r"(r[0]), "=r"(r[1]), "=r"(r[2]), "=r"(r[3]) : "r"(saddr));
}
__device__ __forceinline__ void cp_async16(void* smem, const void* gmem) {
    uint32_t s = (uint32_t)__cvta_generic_to_shared(smem);
    asm volatile("cp.async.cg.shared.global [%0], [%1], 16;" :: "r"(s), "l"(gmem));
}
#define CP_COMMIT asm volatile("cp.async.commit_group;")
#define CP_WAIT2  asm volatile("cp.async.wait_group 2;")
#define CP_WAIT1  asm volatile("cp.async.wait_group 1;")
#define CP_WAIT0  asm volatile("cp.async.wait_group 0;")

// ---------------------------------------------------------------------------
// Kernel 1: 3x3 SAME conv on 16x16x3 token image + head split -> fp16
// ---------------------------------------------------------------------------
__global__ void conv_heads_kernel(const float* __restrict__ q,
                                  const float* __restrict__ k,
                                  const float* __restrict__ v,
                                  const float* __restrict__ w) {
    __shared__ float img[768];
    __shared__ float wt[81];
    int token = blockIdx.x;
    int which = blockIdx.y;
    int tid = threadIdx.x;

    const float* src = (which == 0) ? q : (which == 1) ? k : v;
    __half* dst = (which == 0) ? g_qh : (which == 1) ? g_kh : g_vh;

    const float* xp = src + (size_t)token * DIM_;
    for (int i = tid; i < 768; i += 256) img[i] = xp[i];
    if (tid < 81) wt[tid] = w[tid];
    __syncthreads();

    int s = tid >> 4, t = tid & 15;
    float acc0 = 0.f, acc1 = 0.f, acc2 = 0.f;
#pragma unroll
    for (int dy = 0; dy < 3; ++dy) {
        int ys = s + dy - 1;
        bool vy = ((unsigned)ys < 16u);
#pragma unroll
        for (int dx = 0; dx < 3; ++dx) {
            int xs = t + dx - 1;
            if (vy && ((unsigned)xs < 16u)) {
                int base = (ys * 16 + xs) * 3;
                int wb = (dy * 3 + dx) * 9;
#pragma unroll
                for (int ci = 0; ci < 3; ++ci) {
                    float pv = img[base + ci];
                    acc0 += pv * wt[wb + ci * 3 + 0];
                    acc1 += pv * wt[wb + ci * 3 + 1];
                    acc2 += pv * wt[wb + ci * 3 + 2];
                }
            }
        }
    }
    int b = token >> 10, n = token & 1023;
    float accs[3] = {acc0, acc1, acc2};
    int p = tid * 3;
#pragma unroll
    for (int co = 0; co < 3; ++co) {
        int pp = p + co;
        int h = pp / 96;
        int d = pp - h * 96;
        dst[(((size_t)b * H_ + h) * N_ + n) * HD_ + d] = __float2half_rn(accs[co]);
    }
}

// ---------------------------------------------------------------------------
// Kernel 2: batched tiled transpose: (batch,R,C) -> (batch,C,R), TI -> half
// ---------------------------------------------------------------------------
template<typename TI>
__global__ void transpose_kernel(const TI* __restrict__ in, __half* __restrict__ out,
                                 int R, int C) {
    __shared__ float t[32][33];
    int c0 = blockIdx.x * 32, r0 = blockIdx.y * 32;
    const TI* ip = in + (size_t)blockIdx.z * R * C;
    __half* op = out + (size_t)blockIdx.z * R * C;
    int x = threadIdx.x, y = threadIdx.y;
#pragma unroll
    for (int i = 0; i < 32; i += 8)
        t[y + i][x] = (float)ip[(size_t)(r0 + y + i) * C + c0 + x];
    __syncthreads();
#pragma unroll
    for (int i = 0; i < 32; i += 8)
        op[(size_t)(c0 + y + i) * R + r0 + x] = __float2half_rn(t[x][y + i]);
}

// ---------------------------------------------------------------------------
// FP16 NT GEMM (fp32 accum), cp.async 3-stage pipeline, ldmatrix fragments.
// C[m][n] = scale * sum_k A[m][k]*Bt[n][k] (+ bias[n]).
// 128 threads = 4 warps (2x2). CTA tile 128 x BN, warp tile 64 x WN (WN=BN/2).
// BK=32 halves. Smem rows stride 20 uints (80B) -> conflict-free ldmatrix.
// Dynamic smem: 3*(128+BN)*20 uints.
// ---------------------------------------------------------------------------
template<int BN, bool HALF_OUT>
__global__ __launch_bounds__(128, 2)
void f16_gemm_nt(const __half* __restrict__ A, const __half* __restrict__ Bt,
                 void* __restrict__ Cv,
                 int K, int lda, int ldb, int ldc,
                 long long sA, long long sB, long long sCo, long long sCi,
                 float scale, const float* __restrict__ bias) {
    constexpr int WN = BN / 2;
    constexpr int NF = WN / 8;              // 8 (BN=128) or 6 (BN=96)
    extern __shared__ __align__(16) uint32_t smraw[];
    uint32_t* As0 = smraw;                  // 3 stages x 128*20
    uint32_t* Bs0 = smraw + 3 * 128 * 20;   // 3 stages x BN*20

    int z = blockIdx.z;
    A += (size_t)z * sA;
    Bt += (size_t)z * sB;
    size_t coff = (size_t)(z >> 3) * sCo + (size_t)(z & 7) * sCi;

    int tid = threadIdx.x;
    int lane = tid & 31, w = tid >> 5;
    int wm = w >> 1, wn = w & 1;
    int gid = lane >> 2, tig = lane & 3;
    int m0 = blockIdx.y * 128, n0 = blockIdx.x * BN;

    // per-lane ldmatrix offsets (bytes within tile)
    int lt = lane >> 3, lr = lane & 7;
    int a_lane_off = ((lt & 1) * 8 + lr) * 80 + (lt >> 1) * 16;
    int b_lane_off = ((lt >> 1) * 8 + lr) * 80 + (lt & 1) * 16;

    float acc[4][NF][4];
#pragma unroll
    for (int i = 0; i < 4; ++i)
#pragma unroll
        for (int j = 0; j < NF; ++j)
#pragma unroll
            for (int r = 0; r < 4; ++r) acc[i][j][r] = 0.f;

    int T = K >> 5;   // BK = 32 halves

    auto load_tile = [&](int t, int stg) {
        int k0 = t * 32;
        uint32_t* Asg = As0 + stg * (128 * 20);
        uint32_t* Bsg = Bs0 + stg * (BN * 20);
#pragma unroll
        for (int it = 0; it < 4; ++it) {
            int idx = tid + it * 128;
            int row = idx >> 2, c = idx & 3;          // c: 16B chunk = 8 halves
            cp_async16(&Asg[row * 20 + c * 4],
                       &A[(size_t)(m0 + row) * lda + k0 + c * 8]);
        }
#pragma unroll
        for (int it = 0; it < (BN * 4 + 127) / 128; ++it) {
            int idx = tid + it * 128;
            if (BN == 128 || idx < BN * 4) {
                int row = idx >> 2, c = idx & 3;
                cp_async16(&Bsg[row * 20 + c * 4],
                           &Bt[(size_t)(n0 + row) * ldb + k0 + c * 8]);
            }
        }
    };

    load_tile(0, 0); CP_COMMIT;
    if (T > 1) { load_tile(1, 1); CP_COMMIT; }

    int cur = 0;
    for (int t = 0; t < T; ++t) {
        if (t + 2 < T) { load_tile(t + 2, (t + 2) % 3); CP_COMMIT; CP_WAIT2; }
        else if (t + 1 < T) { CP_WAIT1; }
        else { CP_WAIT0; }
        __syncthreads();

        uint32_t abase = (uint32_t)__cvta_generic_to_shared(As0 + cur * (128 * 20));
        uint32_t bbase = (uint32_t)__cvta_generic_to_shared(Bs0 + cur * (BN * 20));
#pragma unroll
        for (int kk = 0; kk < 16; kk += 8) {   // 2 k-groups of 16 halves
            int kk4 = kk * 4;
            uint32_t a[4][4];
#pragma unroll
            for (int i = 0; i < 4; ++i)
                ldm_x4(a[i], abase + (wm * 64 + i * 16) * 80 + kk4 + a_lane_off);
            uint32_t bf[NF * 2];
#pragma unroll
            for (int p = 0; p < NF / 2; ++p)
                ldm_x4(&bf[p * 4], bbase + (wn * WN + p * 16) * 80 + kk4 + b_lane_off);
#pragma unroll
            for (int i = 0; i < 4; ++i)
#pragma unroll
                for (int j = 0; j < NF; ++j)
                    mma_f16(acc[i][j], a[i], &bf[j * 2]);
        }
        __syncthreads();
        cur = (cur + 1 == 3) ? 0 : cur + 1;
    }

    // direct epilogue
#pragma unroll
    for (int i = 0; i < 4; ++i) {
        int r = m0 + wm * 64 + i * 16 + gid;
#pragma unroll
        for (int j = 0; j < NF; ++j) {
            int cgl = n0 + wn * WN + j * 8 + tig * 2;
            float x0 = acc[i][j][0] * scale, y0 = acc[i][j][1] * scale;
            float x1 = acc[i][j][2] * scale, y1 = acc[i][j][3] * scale;
            if (bias) {
                float bx = bias[cgl], by = bias[cgl + 1];
                x0 += bx; y0 += by; x1 += bx; y1 += by;
            }
            if (HALF_OUT) {
                __half* C = (__half*)Cv + coff;
                *(__half2*)&C[(size_t)r * ldc + cgl] = __floats2half2_rn(x0, y0);
                *(__half2*)&C[(size_t)(r + 8) * ldc + cgl] = __floats2half2_rn(x1, y1);
            } else {
                float* C = (float*)Cv + coff;
                *(float2*)&C[(size_t)r * ldc + cgl] = make_float2(x0, y0);
                *(float2*)&C[(size_t)(r + 8) * ldc + cgl] = make_float2(x1, y1);
            }
        }
    }
}

// ---------------------------------------------------------------------------
// Fused softmax + 8x8 head mix + BN. Reads S fp16, half2 exp (ex2.f16x2),
// fp32 normalizer + fp32 mix, writes P fp16. One block per (b,n).
// ---------------------------------------------------------------------------
__global__ __launch_bounds__(256)
void softmax_mix_kernel(const float* __restrict__ rw, const float* __restrict__ rb,
                        const float* __restrict__ gamma, const float* __restrict__ beta,
                        const float* __restrict__ mean, const float* __restrict__ var) {
    __shared__ __half2 buf[8][512];
    __shared__ float Wm[8][8];
    __shared__ float Cm[8];
    __shared__ float invsS[8];
    int tid = threadIdx.x;
    int bn = blockIdx.x;
    int b = bn >> 10, n = bn & 1023;

    if (tid < 64) {
        int h = tid >> 3, g = tid & 7;
        float inv = gamma[g] * rsqrtf(var[g] + 1e-3f);
        Wm[h][g] = rw[h * 8 + g] * inv;
        if (h == 0) Cm[g] = (rb[g] - mean[g]) * inv + beta[g];
    }

    size_t base = (size_t)b * 8388608 + (size_t)n * 1024;
    const uint4* gin = (const uint4*)(g_s + base);   // per head: 128 uint4
#pragma unroll
    for (int i = 0; i < 4; ++i) {
        int idx = tid + i * 256;                     // 0..1023
        int h = idx >> 7, m16 = idx & 127;
        ((uint4*)&buf[h][0])[m16] = gin[(size_t)h * 131072 + m16];
    }
    __syncthreads();

    // warp w handles head w: max + exp(half2) + fp32 sum
    int w = tid >> 5, lane = tid & 31;
    __half2 m2 = buf[w][lane];
#pragma unroll
    for (int ii = 1; ii < 16; ++ii) m2 = __hmax2(m2, buf[w][lane + ii * 32]);
#pragma unroll
    for (int o = 16; o > 0; o >>= 1) {
        uint32_t u = *(uint32_t*)&m2;
        u = __shfl_xor_sync(0xffffffffu, u, o);
        m2 = __hmax2(m2, *(__half2*)&u);
    }
    __half mx = __hmax(__low2half(m2), __high2half(m2));
    __half2 mx2 = __half2half2(mx);
    const __half2 l2e = __float2half2_rn(1.44269504f);
    float s = 0.f;
#pragma unroll
    for (int ii = 0; ii < 16; ++ii) {
        __half2 v = buf[w][lane + ii * 32];
        __half2 e = h2exp2(__hmul2(__hsub2(v, mx2), l2e));
        buf[w][lane + ii * 32] = e;
        float2 f = __half22float2(e);
        s += f.x + f.y;
    }
#pragma unroll
    for (int o = 16; o > 0; o >>= 1) s += __shfl_xor_sync(0xffffffffu, s, o);
    if (lane == 0) invsS[w] = 1.0f / s;
    __syncthreads();

    // mix heads in fp32 (normalization folded), 4 columns per thread
    float4 p[8];
#pragma unroll
    for (int h = 0; h < 8; ++h) {
        float2 raw = ((const float2*)&buf[h][0])[tid];   // 2 half2 = 4 halves
        __half2 lo = *(__half2*)&raw.x, hi = *(__half2*)&raw.y;
        float2 f0 = __half22float2(lo), f1 = __half22float2(hi);
        float inv = invsS[h];
        p[h] = make_float4(f0.x * inv, f0.y * inv, f1.x * inv, f1.y * inv);
    }
    float2* gout = (float2*)(g_p + base);                // 8B = 4 halves
#pragma unroll
    for (int g = 0; g < 8; ++g) {
        float c = Cm[g];
        float4 o = make_float4(c, c, c, c);
#pragma unroll
        for (int h = 0; h < 8; ++h) {
            float wv = Wm[h][g];
            o.x += p[h].x * wv; o.y += p[h].y * wv;
            o.z += p[h].z * wv; o.w += p[h].w * wv;
        }
        float2 st;
        *(__half2*)&st.x = __floats2half2_rn(o.x, o.y);
        *(__half2*)&st.y = __floats2half2_rn(o.z, o.w);
        gout[(size_t)g * 262144 + tid] = st;
    }
}

// ---------------------------------------------------------------------------
extern "C" void kernel_launch(void* const* d_in, const int* in_sizes, int n_in,
                              void* d_out, int out_size) {
    const float* q      = (const float*)d_in[0];
    const float* k      = (const float*)d_in[1];
    const float* v      = (const float*)d_in[2];
    const float* conv_w = (const float*)d_in[3];
    const float* rw     = (const float*)d_in[4];
    const float* rb     = (const float*)d_in[5];
    const float* gamma  = (const float*)d_in[6];
    const float* beta   = (const float*)d_in[7];
    const float* mean   = (const float*)d_in[8];
    const float* var    = (const float*)d_in[9];
    const float* pw     = (const float*)d_in[10];
    const float* pb     = (const float*)d_in[11];
    float* out = (float*)d_out;

    float scale = 1.0f / sqrtf((float)HD_);

    __half *qh, *kh, *vh, *vt, *wt, *sS, *pp, *ctx;
    cudaGetSymbolAddress((void**)&qh, g_qh);
    cudaGetSymbolAddress((void**)&kh, g_kh);
    cudaGetSymbolAddress((void**)&vh, g_vh);
    cudaGetSymbolAddress((void**)&vt, g_vt);
    cudaGetSymbolAddress((void**)&wt, g_wt);
    cudaGetSymbolAddress((void**)&sS, g_s);
    cudaGetSymbolAddress((void**)&pp, g_p);
    cudaGetSymbolAddress((void**)&ctx, g_ctx);

    const int SM128 = 3 * (128 + 128) * 20 * 4;   // 61440 B
    const int SM96  = 3 * (128 + 96) * 20 * 4;    // 53760 B
    cudaFuncSetAttribute(f16_gemm_nt<128, true>,
                         cudaFuncAttributeMaxDynamicSharedMemorySize, SM128);
    cudaFuncSetAttribute(f16_gemm_nt<96, true>,
                         cudaFuncAttributeMaxDynamicSharedMemorySize, SM96);
    cudaFuncSetAttribute(f16_gemm_nt<128, false>,
                         cudaFuncAttributeMaxDynamicSharedMemorySize, SM128);

    // 1. conv + head split (fp16 outputs)
    conv_heads_kernel<<<dim3(B_ * N_, 3), 256>>>(q, k, v, conv_w);

    // 2. transposes: V(half) -> (B,H,96,N) half, W(float) -> [n][k] half
    transpose_kernel<__half><<<dim3(HD_ / 32, N_ / 32, B_ * H_), dim3(32, 8)>>>(vh, vt, N_, HD_);
    transpose_kernel<float><<<dim3(DIM_ / 32, DIM_ / 32, 1), dim3(32, 8)>>>(pw, wt, DIM_, DIM_);

    // 3. QK^T (scaled) -> S fp16
    f16_gemm_nt<128, true><<<dim3(N_ / 128, N_ / 128, B_ * H_), 128, SM128>>>(
        qh, kh, sS, HD_, HD_, HD_, N_,
        (long long)N_ * HD_, (long long)N_ * HD_,
        (long long)H_ * N_ * N_, (long long)N_ * N_,
        scale, nullptr);

    // 4. softmax + head mix + BN -> P fp16
    softmax_mix_kernel<<<B_ * N_, 256>>>(rw, rb, gamma, beta, mean, var);

    // 5. AV -> ctx (B,N,768) fp16
    f16_gemm_nt<96, true><<<dim3(1, N_ / 128, B_ * H_), 128, SM96>>>(
        pp, vt, ctx, N_, N_, N_, DIM_,
        (long long)N_ * N_, (long long)HD_ * N_,
        (long long)N_ * DIM_, (long long)HD_,
        1.0f, nullptr);

    // 6. projection + bias -> out fp32
    f16_gemm_nt<128, false><<<dim3(DIM_ / 128, (B_ * N_) / 128, 1), 128, SM128>>>(
        ctx, wt, out, DIM_, DIM_, DIM_, DIM_,
        0LL, 0LL, 0LL, 0LL,
        1.0f, pb);
}

// round 11
// speedup vs baseline: 4.8381x; 1.0304x over previous
#include <cuda_runtime.h>
#include <cuda_fp16.h>
#include <math.h>
#include <stdint.h>

// Problem constants
#define B_   8
#define N_   1024
#define DIM_ 768
#define H_   8
#define HD_  96

// ---------------- scratch (device globals; no allocation allowed) ----------
__device__ __align__(256) __half g_qh[B_*H_*N_*HD_];   // (B,H,N,96) fp16
__device__ __align__(256) __half g_kh[B_*H_*N_*HD_];
__device__ __align__(256) __half g_vh[B_*H_*N_*HD_];
__device__ __align__(256) __half g_vt[B_*H_*HD_*N_];   // (B,H,96,N) fp16
__device__ __align__(256) __half g_wt[DIM_*DIM_];      // proj W^T [n][k] fp16
__device__ __align__(256) __half g_s[67108864];        // S logits (B,H,N,N) fp16
__device__ __align__(256) __half g_p[67108864];        // P (post softmax+mix) fp16
__device__ __align__(256) __half g_ctx[B_*N_*DIM_];    // (B,N,768) fp16

// ---------------------------------------------------------------------------
__device__ __forceinline__ void mma_f16(float* c, const uint32_t* a, const uint32_t* b) {
    asm volatile(
        "mma.sync.aligned.m16n8k16.row.col.f32.f16.f16.f32 "
        "{%0,%1,%2,%3}, {%4,%5,%6,%7}, {%8,%9}, {%0,%1,%2,%3};"
        : "+f"(c[0]), "+f"(c[1]), "+f"(c[2]), "+f"(c[3])
        : "r"(a[0]), "r"(a[1]), "r"(a[2]), "r"(a[3]), "r"(b[0]), "r"(b[1]));
}
__device__ __forceinline__ void ldm_x4(uint32_t* r, uint32_t saddr) {
    asm volatile("ldmatrix.sync.aligned.m8n8.x4.shared.b16 {%0,%1,%2,%3}, [%4];"
        : "=r"(r[0]), "=r"(r[1]), "=r"(r[2]), "=r"(r[3]) : "r"(saddr));
}
__device__ __forceinline__ void cp_async16(void* smem, const void* gmem) {
    uint32_t s = (uint32_t)__cvta_generic_to_shared(smem);
    asm volatile("cp.async.cg.shared.global [%0], [%1], 16;" :: "r"(s), "l"(gmem));
}
#define CP_COMMIT asm volatile("cp.async.commit_group;")
#define CP_WAIT2  asm volatile("cp.async.wait_group 2;")
#define CP_WAIT1  asm volatile("cp.async.wait_group 1;")
#define CP_WAIT0  asm volatile("cp.async.wait_group 0;")

// ---------------------------------------------------------------------------
// Kernel 1: 3x3 SAME conv on 16x16x3 token image + head split -> fp16
// ---------------------------------------------------------------------------
__global__ void conv_heads_kernel(const float* __restrict__ q,
                                  const float* __restrict__ k,
                                  const float* __restrict__ v,
                                  const float* __restrict__ w) {
    __shared__ float img[768];
    __shared__ float wt[81];
    int token = blockIdx.x;
    int which = blockIdx.y;
    int tid = threadIdx.x;

    const float* src = (which == 0) ? q : (which == 1) ? k : v;
    __half* dst = (which == 0) ? g_qh : (which == 1) ? g_kh : g_vh;

    const float* xp = src + (size_t)token * DIM_;
    for (int i = tid; i < 768; i += 256) img[i] = xp[i];
    if (tid < 81) wt[tid] = w[tid];
    __syncthreads();

    int s = tid >> 4, t = tid & 15;
    float acc0 = 0.f, acc1 = 0.f, acc2 = 0.f;
#pragma unroll
    for (int dy = 0; dy < 3; ++dy) {
        int ys = s + dy - 1;
        bool vy = ((unsigned)ys < 16u);
#pragma unroll
        for (int dx = 0; dx < 3; ++dx) {
            int xs = t + dx - 1;
            if (vy && ((unsigned)xs < 16u)) {
                int base = (ys * 16 + xs) * 3;
                int wb = (dy * 3 + dx) * 9;
#pragma unroll
                for (int ci = 0; ci < 3; ++ci) {
                    float pv = img[base + ci];
                    acc0 += pv * wt[wb + ci * 3 + 0];
                    acc1 += pv * wt[wb + ci * 3 + 1];
                    acc2 += pv * wt[wb + ci * 3 + 2];
                }
            }
        }
    }
    int b = token >> 10, n = token & 1023;
    float accs[3] = {acc0, acc1, acc2};
    int p = tid * 3;
#pragma unroll
    for (int co = 0; co < 3; ++co) {
        int pp = p + co;
        int h = pp / 96;
        int d = pp - h * 96;
        dst[(((size_t)b * H_ + h) * N_ + n) * HD_ + d] = __float2half_rn(accs[co]);
    }
}

// ---------------------------------------------------------------------------
// Kernel 2: batched tiled transpose: (batch,R,C) -> (batch,C,R), TI -> half
// ---------------------------------------------------------------------------
template<typename TI>
__global__ void transpose_kernel(const TI* __restrict__ in, __half* __restrict__ out,
                                 int R, int C) {
    __shared__ float t[32][33];
    int c0 = blockIdx.x * 32, r0 = blockIdx.y * 32;
    const TI* ip = in + (size_t)blockIdx.z * R * C;
    __half* op = out + (size_t)blockIdx.z * R * C;
    int x = threadIdx.x, y = threadIdx.y;
#pragma unroll
    for (int i = 0; i < 32; i += 8)
        t[y + i][x] = (float)ip[(size_t)(r0 + y + i) * C + c0 + x];
    __syncthreads();
#pragma unroll
    for (int i = 0; i < 32; i += 8)
        op[(size_t)(c0 + y + i) * R + r0 + x] = __float2half_rn(t[x][y + i]);
}

// ---------------------------------------------------------------------------
// FP16 NT GEMM (fp32 accum), 4-stage cp.async ring, ONE barrier per k-tile.
// C[m][n] = scale * sum_k A[m][k]*Bt[n][k] (+ bias[n]).
// 128 threads = 4 warps (2x2). CTA tile 128 x BN, warp tile 64 x WN (WN=BN/2).
// BK=32 halves. Smem rows stride 20 uints (80B) -> conflict-free ldmatrix.
// Safety: load(t+2) (issued before iter-t barrier) writes stage (t+2)%4,
// last computed at iter t-2, which every warp has finished (it passed the
// iter t-1 barrier). So no trailing barrier is needed.
// ---------------------------------------------------------------------------
template<int BN, bool HALF_OUT>
__global__ __launch_bounds__(128, 2)
void f16_gemm_nt(const __half* __restrict__ A, const __half* __restrict__ Bt,
                 void* __restrict__ Cv,
                 int K, int lda, int ldb, int ldc,
                 long long sA, long long sB, long long sCo, long long sCi,
                 float scale, const float* __restrict__ bias) {
    constexpr int WN = BN / 2;
    constexpr int NF = WN / 8;              // 8 (BN=128) or 6 (BN=96)
    constexpr int ASTRIDE = 128 * 20;
    constexpr int BSTRIDE = BN * 20;
    extern __shared__ __align__(16) uint32_t smraw[];
    uint32_t* As0 = smraw;                  // 4 stages x 128*20
    uint32_t* Bs0 = smraw + 4 * ASTRIDE;    // 4 stages x BN*20

    int z = blockIdx.z;
    A += (size_t)z * sA;
    Bt += (size_t)z * sB;
    size_t coff = (size_t)(z >> 3) * sCo + (size_t)(z & 7) * sCi;

    int tid = threadIdx.x;
    int lane = tid & 31, w = tid >> 5;
    int wm = w >> 1, wn = w & 1;
    int gid = lane >> 2, tig = lane & 3;
    int m0 = blockIdx.y * 128, n0 = blockIdx.x * BN;

    // per-lane ldmatrix offsets (bytes within tile)
    int lt = lane >> 3, lr = lane & 7;
    int a_lane_off = ((lt & 1) * 8 + lr) * 80 + (lt >> 1) * 16;
    int b_lane_off = ((lt >> 1) * 8 + lr) * 80 + (lt & 1) * 16;

    float acc[4][NF][4];
#pragma unroll
    for (int i = 0; i < 4; ++i)
#pragma unroll
        for (int j = 0; j < NF; ++j)
#pragma unroll
            for (int r = 0; r < 4; ++r) acc[i][j][r] = 0.f;

    int T = K >> 5;   // BK = 32 halves

    auto load_tile = [&](int t, int stg) {
        int k0 = t * 32;
        uint32_t* Asg = As0 + stg * ASTRIDE;
        uint32_t* Bsg = Bs0 + stg * BSTRIDE;
#pragma unroll
        for (int it = 0; it < 4; ++it) {
            int idx = tid + it * 128;
            int row = idx >> 2, c = idx & 3;          // c: 16B chunk = 8 halves
            cp_async16(&Asg[row * 20 + c * 4],
                       &A[(size_t)(m0 + row) * lda + k0 + c * 8]);
        }
#pragma unroll
        for (int it = 0; it < (BN * 4 + 127) / 128; ++it) {
            int idx = tid + it * 128;
            if (BN == 128 || idx < BN * 4) {
                int row = idx >> 2, c = idx & 3;
                cp_async16(&Bsg[row * 20 + c * 4],
                           &Bt[(size_t)(n0 + row) * ldb + k0 + c * 8]);
            }
        }
    };

    load_tile(0, 0); CP_COMMIT;
    if (T > 1) { load_tile(1, 1); CP_COMMIT; }

    for (int t = 0; t < T; ++t) {
        if (t + 2 < T) { load_tile(t + 2, (t + 2) & 3); CP_COMMIT; CP_WAIT2; }
        else if (t + 1 < T) { CP_WAIT1; }
        else { CP_WAIT0; }
        __syncthreads();

        int cur = t & 3;
        uint32_t abase = (uint32_t)__cvta_generic_to_shared(As0 + cur * ASTRIDE);
        uint32_t bbase = (uint32_t)__cvta_generic_to_shared(Bs0 + cur * BSTRIDE);
#pragma unroll
        for (int kk = 0; kk < 16; kk += 8) {   // 2 k-groups of 16 halves
            int kk4 = kk * 4;
            uint32_t a[4][4];
#pragma unroll
            for (int i = 0; i < 4; ++i)
                ldm_x4(a[i], abase + (wm * 64 + i * 16) * 80 + kk4 + a_lane_off);
            uint32_t bf[NF * 2];
#pragma unroll
            for (int p = 0; p < NF / 2; ++p)
                ldm_x4(&bf[p * 4], bbase + (wn * WN + p * 16) * 80 + kk4 + b_lane_off);
#pragma unroll
            for (int i = 0; i < 4; ++i)
#pragma unroll
                for (int j = 0; j < NF; ++j)
                    mma_f16(acc[i][j], a[i], &bf[j * 2]);
        }
        // no trailing barrier (4-stage ring makes it safe)
    }

    // direct epilogue
#pragma unroll
    for (int i = 0; i < 4; ++i) {
        int r = m0 + wm * 64 + i * 16 + gid;
#pragma unroll
        for (int j = 0; j < NF; ++j) {
            int cgl = n0 + wn * WN + j * 8 + tig * 2;
            float x0 = acc[i][j][0] * scale, y0 = acc[i][j][1] * scale;
            float x1 = acc[i][j][2] * scale, y1 = acc[i][j][3] * scale;
            if (bias) {
                float bx = bias[cgl], by = bias[cgl + 1];
                x0 += bx; y0 += by; x1 += bx; y1 += by;
            }
            if (HALF_OUT) {
                __half* C = (__half*)Cv + coff;
                *(__half2*)&C[(size_t)r * ldc + cgl] = __floats2half2_rn(x0, y0);
                *(__half2*)&C[(size_t)(r + 8) * ldc + cgl] = __floats2half2_rn(x1, y1);
            } else {
                float* C = (float*)Cv + coff;
                *(float2*)&C[(size_t)r * ldc + cgl] = make_float2(x0, y0);
                *(float2*)&C[(size_t)(r + 8) * ldc + cgl] = make_float2(x1, y1);
            }
        }
    }
}

// ---------------------------------------------------------------------------
// Fused softmax + 8x8 head mix + BN. Register-resident per-warp softmax:
// warp w owns head w (gmem -> regs -> max/exp/sum -> normalized fp16 -> smem),
// then the transpose-read mix. One block (256 thr) per (b,n).
// ---------------------------------------------------------------------------
__global__ __launch_bounds__(256)
void softmax_mix_kernel(const float* __restrict__ rw, const float* __restrict__ rb,
                        const float* __restrict__ gamma, const float* __restrict__ beta,
                        const float* __restrict__ mean, const float* __restrict__ var) {
    __shared__ __half2 buf[8][512];
    __shared__ float Wm[8][8];
    __shared__ float Cm[8];
    int tid = threadIdx.x;
    int bn = blockIdx.x;
    int b = bn >> 10, n = bn & 1023;

    if (tid < 64) {
        int h = tid >> 3, g = tid & 7;
        float inv = gamma[g] * rsqrtf(var[g] + 1e-3f);
        Wm[h][g] = rw[h * 8 + g] * inv;
        if (h == 0) Cm[g] = (rb[g] - mean[g]) * inv + beta[g];
    }

    int w = tid >> 5, lane = tid & 31;
    size_t base = (size_t)b * 8388608 + (size_t)n * 1024;

    // load head w's row into registers: 4 uint4 = 16 half2 per lane
    const uint4* src = (const uint4*)(g_s + base + (size_t)w * 1048576);
    uint4 raw[4];
#pragma unroll
    for (int j = 0; j < 4; ++j) raw[j] = src[lane + j * 32];
    __half2* vh2 = (__half2*)raw;   // 16 half2, linear in m

    // max (fp16), reduce across warp
    __half2 m2 = vh2[0];
#pragma unroll
    for (int ii = 1; ii < 16; ++ii) m2 = __hmax2(m2, vh2[ii]);
#pragma unroll
    for (int o = 16; o > 0; o >>= 1) {
        uint32_t u = *(uint32_t*)&m2;
        u = __shfl_xor_sync(0xffffffffu, u, o);
        m2 = __hmax2(m2, *(__half2*)&u);
    }
    __half2 mx2 = __half2half2(__hmax(__low2half(m2), __high2half(m2)));
    const __half2 l2e = __float2half2_rn(1.44269504f);

    // exp in fp16 (ex2.f16x2), fp32 sum
    float s = 0.f;
#pragma unroll
    for (int ii = 0; ii < 16; ++ii) {
        __half2 e = h2exp2(__hmul2(__hsub2(vh2[ii], mx2), l2e));
        vh2[ii] = e;
        float2 f = __half22float2(e);
        s += f.x + f.y;
    }
#pragma unroll
    for (int o = 16; o > 0; o >>= 1) s += __shfl_xor_sync(0xffffffffu, s, o);
    __half2 inv2 = __float2half2_rn(1.0f / s);

    // normalize in fp16 (P is fp16 downstream anyway), store to smem
#pragma unroll
    for (int ii = 0; ii < 16; ++ii) vh2[ii] = __hmul2(vh2[ii], inv2);
    uint4* brow = (uint4*)&buf[w][0];
#pragma unroll
    for (int j = 0; j < 4; ++j) brow[lane + j * 32] = raw[j];
    __syncthreads();

    // mix heads in fp32, 4 columns (m = 4*tid..4*tid+3) per thread
    float4 p[8];
#pragma unroll
    for (int h = 0; h < 8; ++h) {
        float2 rawm = ((const float2*)&buf[h][0])[tid];   // 2 half2 = 4 halves
        __half2 lo = *(__half2*)&rawm.x, hi = *(__half2*)&rawm.y;
        float2 f0 = __half22float2(lo), f1 = __half22float2(hi);
        p[h] = make_float4(f0.x, f0.y, f1.x, f1.y);
    }
    float2* gout = (float2*)(g_p + base);                // 8B = 4 halves
#pragma unroll
    for (int g = 0; g < 8; ++g) {
        float c = Cm[g];
        float4 o = make_float4(c, c, c, c);
#pragma unroll
        for (int h = 0; h < 8; ++h) {
            float wv = Wm[h][g];
            o.x += p[h].x * wv; o.y += p[h].y * wv;
            o.z += p[h].z * wv; o.w += p[h].w * wv;
        }
        float2 st;
        *(__half2*)&st.x = __floats2half2_rn(o.x, o.y);
        *(__half2*)&st.y = __floats2half2_rn(o.z, o.w);
        gout[(size_t)g * 262144 + tid] = st;
    }
}

// ---------------------------------------------------------------------------
extern "C" void kernel_launch(void* const* d_in, const int* in_sizes, int n_in,
                              void* d_out, int out_size) {
    const float* q      = (const float*)d_in[0];
    const float* k      = (const float*)d_in[1];
    const float* v      = (const float*)d_in[2];
    const float* conv_w = (const float*)d_in[3];
    const float* rw     = (const float*)d_in[4];
    const float* rb     = (const float*)d_in[5];
    const float* gamma  = (const float*)d_in[6];
    const float* beta   = (const float*)d_in[7];
    const float* mean   = (const float*)d_in[8];
    const float* var    = (const float*)d_in[9];
    const float* pw     = (const float*)d_in[10];
    const float* pb     = (const float*)d_in[11];
    float* out = (float*)d_out;

    float scale = 1.0f / sqrtf((float)HD_);

    __half *qh, *kh, *vh, *vt, *wt, *sS, *pp, *ctx;
    cudaGetSymbolAddress((void**)&qh, g_qh);
    cudaGetSymbolAddress((void**)&kh, g_kh);
    cudaGetSymbolAddress((void**)&vh, g_vh);
    cudaGetSymbolAddress((void**)&vt, g_vt);
    cudaGetSymbolAddress((void**)&wt, g_wt);
    cudaGetSymbolAddress((void**)&sS, g_s);
    cudaGetSymbolAddress((void**)&pp, g_p);
    cudaGetSymbolAddress((void**)&ctx, g_ctx);

    const int SM128 = 4 * (128 + 128) * 20 * 4;   // 81920 B
    const int SM96  = 4 * (128 + 96) * 20 * 4;    // 71680 B
    cudaFuncSetAttribute(f16_gemm_nt<128, true>,
                         cudaFuncAttributeMaxDynamicSharedMemorySize, SM128);
    cudaFuncSetAttribute(f16_gemm_nt<96, true>,
                         cudaFuncAttributeMaxDynamicSharedMemorySize, SM96);
    cudaFuncSetAttribute(f16_gemm_nt<128, false>,
                         cudaFuncAttributeMaxDynamicSharedMemorySize, SM128);

    // 1. conv + head split (fp16 outputs)
    conv_heads_kernel<<<dim3(B_ * N_, 3), 256>>>(q, k, v, conv_w);

    // 2. transposes: V(half) -> (B,H,96,N) half, W(float) -> [n][k] half
    transpose_kernel<__half><<<dim3(HD_ / 32, N_ / 32, B_ * H_), dim3(32, 8)>>>(vh, vt, N_, HD_);
    transpose_kernel<float><<<dim3(DIM_ / 32, DIM_ / 32, 1), dim3(32, 8)>>>(pw, wt, DIM_, DIM_);

    // 3. QK^T (scaled) -> S fp16
    f16_gemm_nt<128, true><<<dim3(N_ / 128, N_ / 128, B_ * H_), 128, SM128>>>(
        qh, kh, sS, HD_, HD_, HD_, N_,
        (long long)N_ * HD_, (long long)N_ * HD_,
        (long long)H_ * N_ * N_, (long long)N_ * N_,
        scale, nullptr);

    // 4. softmax + head mix + BN -> P fp16
    softmax_mix_kernel<<<B_ * N_, 256>>>(rw, rb, gamma, beta, mean, var);

    // 5. AV -> ctx (B,N,768) fp16
    f16_gemm_nt<96, true><<<dim3(1, N_ / 128, B_ * H_), 128, SM96>>>(
        pp, vt, ctx, N_, N_, N_, DIM_,
        (long long)N_ * N_, (long long)HD_ * N_,
        (long long)N_ * DIM_, (long long)HD_,
        1.0f, nullptr);

    // 6. projection + bias -> out fp32
    f16_gemm_nt<128, false><<<dim3(DIM_ / 128, (B_ * N_) / 128, 1), 128, SM128>>>(
        ctx, wt, out, DIM_, DIM_, DIM_, DIM_,
        0LL, 0LL, 0LL, 0LL,
        1.0f, pb);
}